// round 6
// baseline (speedup 1.0000x reference)
#include <cuda_runtime.h>
#include <math.h>

#define B_  16
#define L_  128
#define S_  64
#define T_  64
#define QD  1024
#define HD  512
#define OD  512
#define ST_ 4096

typedef unsigned long long u64;
typedef unsigned int u32;

// ---------------- scratch (static device globals) ---------------------------
__device__ float g_q  [B_*L_*HD];
__device__ float g_sk [B_*S_*HD];
__device__ float g_tk [B_*T_*HD];
__device__ float g_sv [B_*S_*HD];
__device__ float g_tv [B_*T_*HD];
__device__ float g_svT[B_*HD*S_];
__device__ float g_tvT[B_*HD*T_];
__device__ float g_w  [(size_t)B_*L_*ST_];       // 33.5 MB
__device__ float g_rs [B_*L_];
__device__ float g_ctx[B_*L_*HD];
__device__ float g_part[128*128*512];            // split-K scratch (33.5 MB)
__device__ float g_wT [5*512*1024 + 512*1536];   // transposed weights (13.6 MB)

// ---------------- small helpers ---------------------------------------------
__device__ __forceinline__ u32 tf32r(float x){
    u32 y; asm("cvt.rna.tf32.f32 %0, %1;":"=r"(y):"f"(x)); return y;
}
__device__ __forceinline__ uint4 cvt4(float4 v){
    uint4 o; o.x=tf32r(v.x); o.y=tf32r(v.y); o.z=tf32r(v.z); o.w=tf32r(v.w); return o;
}
__device__ __forceinline__ u32 smem_u32(const void* p){
    u32 a; asm("{ .reg .u64 t; cvta.to.shared.u64 t, %1; cvt.u32.u64 %0, t; }":"=r"(a):"l"(p));
    return a;
}
__device__ __forceinline__ void mma8(float d[4], const u32 a[4], const u32 b[2]){
    asm volatile("mma.sync.aligned.m16n8k8.row.col.f32.tf32.tf32.f32 "
        "{%0,%1,%2,%3}, {%4,%5,%6,%7}, {%8,%9}, {%0,%1,%2,%3};"
        : "+f"(d[0]),"+f"(d[1]),"+f"(d[2]),"+f"(d[3])
        : "r"(a[0]),"r"(a[1]),"r"(a[2]),"r"(a[3]),"r"(b[0]),"r"(b[1]));
}
#define LDSM4(r0,r1,r2,r3,addr) \
    asm volatile("ldmatrix.sync.aligned.m8n8.x4.shared.b16 {%0,%1,%2,%3}, [%4];" \
        : "=r"(r0),"=r"(r1),"=r"(r2),"=r"(r3) : "r"(addr))

// dynamic smem (floats): A slots @ 0,4096 ; B slots @ 8192,12288  (64 KB total)
#define SMEM_MMA 65536

// ---- shared mma-tile core pieces -------------------------------------------
// Per-lane ldmatrix address precomputation:
//  A x4 load (per mf): m0=(row,seg0) m1=(row+8,seg0) m2=(row,seg1) m3=(row+8,seg1)
//    lane l: q=l>>3 -> row_off=(q&1)*8, seg_half=q>>1
//  B x4 load (per nf-pair p): m0=(nf0,s0) m1=(nf0,s1) m2=(nf1,s0) m3=(nf1,s1)
//    lane l: q=l>>3 -> nf_off=q>>1, seg_half=q&1
//  smem byte addr = row*128 + ((2*ks + seg_half) ^ (row&7))*16, rows 16-aligned
#define MMA_PROLOG() \
    int tid=threadIdx.x, lane=tid&31, wid=tid>>5; \
    int wm = wid&3, wn = wid>>2; \
    int gid = lane>>2, tig = lane&3; \
    int l7 = lane&7, lq = lane>>3; \
    u32 smem_u = smem_u32(dsm); \
    int a_sh = lq>>1, b_sh = lq&1; \
    u32 a_row[2], b_row[4]; \
    _Pragma("unroll") \
    for (int mf=0;mf<2;mf++) a_row[mf] = (u32)(wm*32 + mf*16 + (lq&1)*8 + l7)*128u; \
    _Pragma("unroll") \
    for (int p=0;p<4;p++)    b_row[p]  = (u32)(wn*64 + (2*p + (lq>>1))*8 + l7)*128u; \
    int row_[4], seg_[4]; \
    _Pragma("unroll") \
    for (int j=0;j<4;j++){ int f4 = tid + j*256; row_[j]=f4>>3; seg_[j]=f4&7; } \
    float acc[2][8][4]; \
    _Pragma("unroll") \
    for(int mf=0;mf<2;mf++) \
        _Pragma("unroll") \
        for(int nf=0;nf<8;nf++) \
            _Pragma("unroll") \
            for(int r=0;r<4;r++) acc[mf][nf][r]=0.f; \
    uint4 pa[4], pb[4];

#define MMA_STORE_STAGE(slotbase) do { \
    uint4* A4 = (uint4*)(dsm + (slotbase)); \
    uint4* B4 = (uint4*)(dsm + 8192 + (slotbase)); \
    _Pragma("unroll") \
    for (int j=0;j<4;j++){ \
        A4[row_[j]*8 + (seg_[j]^(row_[j]&7))] = pa[j]; \
        B4[row_[j]*8 + (seg_[j]^(row_[j]&7))] = pb[j]; \
    } \
} while(0)

#define MMA_COMPUTE(slot) do { \
    u32 Ab = smem_u + (u32)(slot)*16384u; \
    u32 Bb = smem_u + 32768u + (u32)(slot)*16384u; \
    _Pragma("unroll") \
    for (int ks=0; ks<4; ks++){ \
        u32 asg = (u32)(((ks*2 + a_sh) ^ l7) << 4); \
        u32 bsg = (u32)(((ks*2 + b_sh) ^ l7) << 4); \
        u32 afr[2][4]; u32 bfr[8][2]; \
        _Pragma("unroll") \
        for (int mf=0;mf<2;mf++) \
            LDSM4(afr[mf][0],afr[mf][1],afr[mf][2],afr[mf][3], Ab + a_row[mf] + asg); \
        _Pragma("unroll") \
        for (int p=0;p<4;p++) \
            LDSM4(bfr[2*p][0],bfr[2*p][1],bfr[2*p+1][0],bfr[2*p+1][1], Bb + b_row[p] + bsg); \
        _Pragma("unroll") \
        for (int mf=0;mf<2;mf++) \
            _Pragma("unroll") \
            for (int nf=0;nf<8;nf++) mma8(acc[mf][nf], afr[mf], bfr[nf]); \
    } \
} while(0)

// ============ trilinear logits via mma.sync: C[128l x 128st] = Q @ P^T ======
__global__ __launch_bounds__(256) void tri_mma(const float* __restrict__ q,
        const float* __restrict__ sk, const float* __restrict__ tk, float* __restrict__ w){
    extern __shared__ __align__(16) float dsm[];
    int tile = blockIdx.x, b = blockIdx.y;
    const float* qb  = q  + (size_t)b*L_*HD;
    const float* skb = sk + (size_t)b*S_*HD;
    const float* tkb = tk + (size_t)b*T_*HD;
    MMA_PROLOG();

    #pragma unroll
    for (int j=0;j<4;j++){
        pa[j] = cvt4(*(const float4*)(qb + (size_t)row_[j]*HD + seg_[j]*4));
        int st = tile*128 + row_[j], s = st>>6, t = st&63;
        float4 a = *(const float4*)(tkb + (size_t)t*HD + seg_[j]*4);
        float4 c = *(const float4*)(skb + (size_t)s*HD + seg_[j]*4);
        pb[j] = cvt4(make_float4(a.x*c.x, a.y*c.y, a.z*c.z, a.w*c.w));
    }
    MMA_STORE_STAGE(0);
    __syncthreads();

    const int NT = HD/32;   // 16
    for (int kt=0; kt<NT; kt++){
        int slot = kt&1;
        if (kt+1 < NT){
            int kc = (kt+1)*32;
            #pragma unroll
            for (int j=0;j<4;j++){
                pa[j] = cvt4(*(const float4*)(qb + (size_t)row_[j]*HD + kc + seg_[j]*4));
                int st = tile*128 + row_[j], s = st>>6, t = st&63;
                float4 a = *(const float4*)(tkb + (size_t)t*HD + kc + seg_[j]*4);
                float4 c = *(const float4*)(skb + (size_t)s*HD + kc + seg_[j]*4);
                pb[j] = cvt4(make_float4(a.x*c.x, a.y*c.y, a.z*c.z, a.w*c.w));
            }
        }
        MMA_COMPUTE(slot);
        if (kt+1 < NT) MMA_STORE_STAGE((slot^1)*4096);
        __syncthreads();
    }

    const float scale = 0.044194173824159216f;  // 1/sqrt(512)
    #pragma unroll
    for (int mf=0;mf<2;mf++){
        int row = wm*32 + mf*16 + gid;
        float* w0 = w + ((size_t)(b*L_+row))*ST_ + tile*128 + wn*64 + tig*2;
        #pragma unroll
        for (int nf=0;nf<8;nf++){
            *(float2*)(w0 + nf*8)          = make_float2(acc[mf][nf][0]*scale, acc[mf][nf][1]*scale);
            *(float2*)(w0 + nf*8 + 8*ST_)  = make_float2(acc[mf][nf][2]*scale, acc[mf][nf][3]*scale);
        }
    }
}

// ====== ctx via mma.sync: part[b,sp][128l x 128k] = E_chunk @ V^T ===========
__global__ __launch_bounds__(256) void ctx_mma(const float* __restrict__ E,
        const float* __restrict__ svT, const float* __restrict__ tvT, float* __restrict__ part){
    extern __shared__ __align__(16) float dsm[];
    int n0 = blockIdx.x*128, sp = blockIdx.y, b = blockIdx.z;
    const float* Eb  = E   + (size_t)b*L_*ST_ + sp*1024;
    const float* svb = svT + ((size_t)b*HD + n0)*S_;
    const float* tvb = tvT + ((size_t)b*HD + n0)*T_;
    MMA_PROLOG();

    {   int st0 = sp*1024, s = st0>>6, tb = st0&63;
        #pragma unroll
        for (int j=0;j<4;j++){
            pa[j] = cvt4(*(const float4*)(Eb + (size_t)row_[j]*ST_ + seg_[j]*4));
            float4 t4 = *(const float4*)(tvb + (size_t)row_[j]*T_ + tb + seg_[j]*4);
            float sc = svb[(size_t)row_[j]*S_ + s];
            pb[j] = cvt4(make_float4(t4.x*sc, t4.y*sc, t4.z*sc, t4.w*sc));
        }
    }
    MMA_STORE_STAGE(0);
    __syncthreads();

    const int NT = 1024/32;  // 32
    for (int kt=0; kt<NT; kt++){
        int slot = kt&1;
        if (kt+1 < NT){
            int kc = (kt+1)*32;
            int st0 = sp*1024 + kc, s = st0>>6, tb = st0&63;
            #pragma unroll
            for (int j=0;j<4;j++){
                pa[j] = cvt4(*(const float4*)(Eb + (size_t)row_[j]*ST_ + kc + seg_[j]*4));
                float4 t4 = *(const float4*)(tvb + (size_t)row_[j]*T_ + tb + seg_[j]*4);
                float sc = svb[(size_t)row_[j]*S_ + s];
                pb[j] = cvt4(make_float4(t4.x*sc, t4.y*sc, t4.z*sc, t4.w*sc));
            }
        }
        MMA_COMPUTE(slot);
        if (kt+1 < NT) MMA_STORE_STAGE((slot^1)*4096);
        __syncthreads();
    }

    #pragma unroll
    for (int mf=0;mf<2;mf++){
        int row = wm*32 + mf*16 + gid;
        float* p0 = part + ((size_t)(b*4+sp)*128 + row)*512 + n0 + wn*64 + tig*2;
        #pragma unroll
        for (int nf=0;nf<8;nf++){
            *(float2*)(p0 + nf*8)         = make_float2(acc[mf][nf][0], acc[mf][nf][1]);
            *(float2*)(p0 + nf*8 + 8*512) = make_float2(acc[mf][nf][2], acc[mf][nf][3]);
        }
    }
}

// ============ projections via mma.sync: C = A[Mx1024] @ W + bias ============
struct ProjArgs {
    const float* A[5];
    const float* WT[5];
    const float* bias[5];
    float*       C[5];
};

__global__ __launch_bounds__(256) void proj_mma(ProjArgs args){
    extern __shared__ __align__(16) float dsm[];
    int y = blockIdx.y;
    int task, mt;
    if (y < 16){ task=0; mt=y; } else { task = 1 + ((y-16)>>3); mt = (y-16)&7; }
    int bm = mt*128, bn = blockIdx.x*128;
    const float* Ab   = args.A[task]  + (size_t)bm*QD;
    const float* Bb   = args.WT[task] + (size_t)bn*QD;
    const float* bias = args.bias[task];
    float*       C    = args.C[task]  + (size_t)bm*OD + bn;
    MMA_PROLOG();

    #pragma unroll
    for (int j=0;j<4;j++){
        pa[j] = cvt4(*(const float4*)(Ab + (size_t)row_[j]*QD + seg_[j]*4));
        pb[j] = cvt4(*(const float4*)(Bb + (size_t)row_[j]*QD + seg_[j]*4));
    }
    MMA_STORE_STAGE(0);
    __syncthreads();

    const int NT = QD/32;  // 32
    for (int kt=0; kt<NT; kt++){
        int slot = kt&1;
        if (kt+1 < NT){
            int kc = (kt+1)*32;
            #pragma unroll
            for (int j=0;j<4;j++){
                pa[j] = cvt4(*(const float4*)(Ab + (size_t)row_[j]*QD + kc + seg_[j]*4));
                pb[j] = cvt4(*(const float4*)(Bb + (size_t)row_[j]*QD + kc + seg_[j]*4));
            }
        }
        MMA_COMPUTE(slot);
        if (kt+1 < NT) MMA_STORE_STAGE((slot^1)*4096);
        __syncthreads();
    }

    const float* bp = bias + bn + wn*64 + tig*2;
    #pragma unroll
    for (int mf=0;mf<2;mf++){
        int row = wm*32 + mf*16 + gid;
        float* c0 = C + (size_t)row*OD + wn*64 + tig*2;
        #pragma unroll
        for (int nf=0;nf<8;nf++){
            float b0 = bp[nf*8], b1 = bp[nf*8+1];
            *(float2*)(c0 + nf*8)        = make_float2(acc[mf][nf][0]+b0, acc[mf][nf][1]+b1);
            *(float2*)(c0 + nf*8 + 8*OD) = make_float2(acc[mf][nf][2]+b0, acc[mf][nf][3]+b1);
        }
    }
}

// ===== out partials via mma.sync: split-K = 3x512 over concat(query,ctx) ====
__global__ __launch_bounds__(256) void out_mma(const float* __restrict__ query,
        const float* __restrict__ ctx, const float* __restrict__ WoT, float* __restrict__ part){
    extern __shared__ __align__(16) float dsm[];
    int bn = blockIdx.x*128, bm = blockIdx.y*128, sp = blockIdx.z;
    const float* Ab; int lda;
    if (sp < 2){ Ab = query + (size_t)bm*QD + sp*512; lda = QD; }
    else       { Ab = ctx   + (size_t)bm*HD;          lda = HD; }
    const float* Bb = WoT + (size_t)bn*1536 + sp*512;
    MMA_PROLOG();

    #pragma unroll
    for (int j=0;j<4;j++){
        pa[j] = cvt4(*(const float4*)(Ab + (size_t)row_[j]*lda + seg_[j]*4));
        pb[j] = cvt4(*(const float4*)(Bb + (size_t)row_[j]*1536 + seg_[j]*4));
    }
    MMA_STORE_STAGE(0);
    __syncthreads();

    const int NT = 512/32;  // 16
    for (int kt=0; kt<NT; kt++){
        int slot = kt&1;
        if (kt+1 < NT){
            int kc = (kt+1)*32;
            #pragma unroll
            for (int j=0;j<4;j++){
                pa[j] = cvt4(*(const float4*)(Ab + (size_t)row_[j]*lda + kc + seg_[j]*4));
                pb[j] = cvt4(*(const float4*)(Bb + (size_t)row_[j]*1536 + kc + seg_[j]*4));
            }
        }
        MMA_COMPUTE(slot);
        if (kt+1 < NT) MMA_STORE_STAGE((slot^1)*4096);
        __syncthreads();
    }

    #pragma unroll
    for (int mf=0;mf<2;mf++){
        int row = wm*32 + mf*16 + gid;
        float* p0 = part + ((size_t)sp*2048 + bm + row)*512 + bn + wn*64 + tig*2;
        #pragma unroll
        for (int nf=0;nf<8;nf++){
            *(float2*)(p0 + nf*8)         = make_float2(acc[mf][nf][0], acc[mf][nf][1]);
            *(float2*)(p0 + nf*8 + 8*512) = make_float2(acc[mf][nf][2], acc[mf][nf][3]);
        }
    }
}

// -------- transpose weights: WT[n][k] = W[k][n]  (N = 512 always) -----------
struct TWArgs { const float* src[6]; float* dst[6]; int K[6]; };
__global__ void transpose_w(TWArgs a){
    __shared__ float tb[64][65];
    int mid = blockIdx.z;
    int K = a.K[mid];
    int k0 = blockIdx.y*64;
    if (k0 >= K) return;
    int n0 = blockIdx.x*64;
    const float* src = a.src[mid];
    float* dst = a.dst[mid];
    int tid = threadIdx.x;
    #pragma unroll
    for (int j=0;j<16;j++){
        int e = tid + j*256, kk = e>>6, nn = e&63;
        tb[nn][kk] = src[(size_t)(k0+kk)*512 + n0+nn];
    }
    __syncthreads();
    #pragma unroll
    for (int j=0;j<16;j++){
        int e = tid + j*256, nn = e>>6, kk = e&63;
        dst[(size_t)(n0+nn)*K + k0+kk] = tb[nn][kk];
    }
}

// -------- transpose sv/tv: vT[b][k][s] = v[b][s][k] ------------------------
__global__ void transpose_vals(const float* __restrict__ sv, const float* __restrict__ tv,
                               float* __restrict__ svT, float* __restrict__ tvT){
    __shared__ float tilebuf[64][65];
    int k0 = blockIdx.x*64, b = blockIdx.y;
    const float* src = blockIdx.z ? tv : sv;
    float* dst = blockIdx.z ? tvT : svT;
    int tid = threadIdx.x;
    #pragma unroll
    for (int j = 0; j < 16; j++){
        int e = tid + j*256, s = e>>6, k = e&63;
        tilebuf[k][s] = src[(size_t)(b*64 + s)*HD + k0 + k];
    }
    __syncthreads();
    #pragma unroll
    for (int j = 0; j < 16; j++){
        int e = tid + j*256, k = e>>6, s = e&63;
        dst[(size_t)(b*HD + k0 + k)*64 + s] = tilebuf[k][s];
    }
}

// ----------- joint softmax over st=4096; stores exp in place + rowsum -------
__global__ void softmax_kernel(float* __restrict__ w, float* __restrict__ rowsum) {
    int row = blockIdx.x;
    float4* p4 = (float4*)(w + (size_t)row * ST_);
    int tid = threadIdx.x;
    float4 v[4];
    float mx = -1e30f;
    #pragma unroll
    for (int i = 0; i < 4; i++) {
        v[i] = p4[tid + i*256];
        mx = fmaxf(mx, fmaxf(fmaxf(v[i].x, v[i].y), fmaxf(v[i].z, v[i].w)));
    }
    __shared__ float red[256];
    red[tid] = mx; __syncthreads();
    #pragma unroll
    for (int s = 128; s > 0; s >>= 1) {
        if (tid < s) red[tid] = fmaxf(red[tid], red[tid+s]);
        __syncthreads();
    }
    mx = red[0];
    __syncthreads();
    float sum = 0.f;
    #pragma unroll
    for (int i = 0; i < 4; i++) {
        float4 e;
        e.x = expf(v[i].x - mx); e.y = expf(v[i].y - mx);
        e.z = expf(v[i].z - mx); e.w = expf(v[i].w - mx);
        sum += (e.x + e.y) + (e.z + e.w);
        p4[tid + i*256] = e;
    }
    red[tid] = sum; __syncthreads();
    #pragma unroll
    for (int s = 128; s > 0; s >>= 1) {
        if (tid < s) red[tid] += red[tid+s];
        __syncthreads();
    }
    if (tid == 0) rowsum[row] = red[0];
}

// reduce the 4 split-K partials, apply 1/rowsum
__global__ void ctx_reduce(const float* __restrict__ part, const float* __restrict__ rs,
                           float* __restrict__ ctx){
    int gid = blockIdx.x*256 + threadIdx.x;       // float4 id over 16*128*128
    int n4 = gid & 127; int rest = gid >> 7; int l = rest & 127; int b = rest >> 7;
    const float4* p = (const float4*)part;
    float4 a = make_float4(0,0,0,0);
    #pragma unroll
    for (int sp=0; sp<4; sp++){
        float4 v = p[ ((size_t)(b*4+sp)*128 + l)*128 + n4 ];
        a.x+=v.x; a.y+=v.y; a.z+=v.z; a.w+=v.w;
    }
    float inv = 1.f / rs[b*128 + l];
    ((float4*)ctx)[gid] = make_float4(a.x*inv, a.y*inv, a.z*inv, a.w*inv);
}

// reduce 3 split-K partials + bias + relu
__global__ void out_reduce(const float* __restrict__ part, const float* __restrict__ bo,
                           float* __restrict__ out){
    int gid = blockIdx.x*256 + threadIdx.x;       // float4 id over 2048*128
    int n4 = gid & 127; int m = gid >> 7;
    float4 p0 = ((const float4*)part)[(size_t)m*128 + n4];
    float4 p1 = ((const float4*)part)[(size_t)(2048+m)*128 + n4];
    float4 p2 = ((const float4*)part)[(size_t)(4096+m)*128 + n4];
    float4 bb = ((const float4*)bo)[n4];
    float4 o = make_float4(fmaxf(p0.x+p1.x+p2.x+bb.x, 0.f), fmaxf(p0.y+p1.y+p2.y+bb.y, 0.f),
                           fmaxf(p0.z+p1.z+p2.z+bb.z, 0.f), fmaxf(p0.w+p1.w+p2.w+bb.w, 0.f));
    ((float4*)out)[gid] = o;
}

// ----------------------------------------------------------------------------
extern "C" void kernel_launch(void* const* d_in, const int* in_sizes, int n_in,
                              void* d_out, int out_size) {
    const float* query = (const float*)d_in[0];
    const float* src   = (const float*)d_in[1];
    const float* trg   = (const float*)d_in[2];
    const float* Wq    = (const float*)d_in[3];
    const float* bq    = (const float*)d_in[4];
    const float* Ws    = (const float*)d_in[5];
    const float* bs    = (const float*)d_in[6];
    const float* Wt    = (const float*)d_in[7];
    const float* bt    = (const float*)d_in[8];
    const float* Wsv   = (const float*)d_in[9];
    const float* bsv   = (const float*)d_in[10];
    const float* Wtv   = (const float*)d_in[11];
    const float* btv   = (const float*)d_in[12];
    const float* Wo    = (const float*)d_in[13];
    const float* bo    = (const float*)d_in[14];
    float* out = (float*)d_out;

    float *gq, *gsk, *gtk, *gsv, *gtv, *gsvT, *gtvT, *gw, *grs, *gctx, *gpart, *gwT;
    cudaGetSymbolAddress((void**)&gq,   g_q);
    cudaGetSymbolAddress((void**)&gsk,  g_sk);
    cudaGetSymbolAddress((void**)&gtk,  g_tk);
    cudaGetSymbolAddress((void**)&gsv,  g_sv);
    cudaGetSymbolAddress((void**)&gtv,  g_tv);
    cudaGetSymbolAddress((void**)&gsvT, g_svT);
    cudaGetSymbolAddress((void**)&gtvT, g_tvT);
    cudaGetSymbolAddress((void**)&gw,   g_w);
    cudaGetSymbolAddress((void**)&grs,  g_rs);
    cudaGetSymbolAddress((void**)&gctx, g_ctx);
    cudaGetSymbolAddress((void**)&gpart,g_part);
    cudaGetSymbolAddress((void**)&gwT,  g_wT);

    static int smem_set = 0;
    if (!smem_set){
        cudaFuncSetAttribute(tri_mma,  cudaFuncAttributeMaxDynamicSharedMemorySize, SMEM_MMA);
        cudaFuncSetAttribute(ctx_mma,  cudaFuncAttributeMaxDynamicSharedMemorySize, SMEM_MMA);
        cudaFuncSetAttribute(proj_mma, cudaFuncAttributeMaxDynamicSharedMemorySize, SMEM_MMA);
        cudaFuncSetAttribute(out_mma,  cudaFuncAttributeMaxDynamicSharedMemorySize, SMEM_MMA);
        smem_set = 1;
    }

    float* WqT  = gwT;
    float* WsT  = gwT + 1*512*1024;
    float* WtT  = gwT + 2*512*1024;
    float* WsvT = gwT + 3*512*1024;
    float* WtvT = gwT + 4*512*1024;
    float* WoT  = gwT + 5*512*1024;

    TWArgs tw;
    tw.src[0]=Wq;  tw.dst[0]=WqT;  tw.K[0]=1024;
    tw.src[1]=Ws;  tw.dst[1]=WsT;  tw.K[1]=1024;
    tw.src[2]=Wt;  tw.dst[2]=WtT;  tw.K[2]=1024;
    tw.src[3]=Wsv; tw.dst[3]=WsvT; tw.K[3]=1024;
    tw.src[4]=Wtv; tw.dst[4]=WtvT; tw.K[4]=1024;
    tw.src[5]=Wo;  tw.dst[5]=WoT;  tw.K[5]=1536;

    ProjArgs pa;
    pa.A[0]=query; pa.A[1]=src;  pa.A[2]=trg;  pa.A[3]=src;   pa.A[4]=trg;
    pa.WT[0]=WqT;  pa.WT[1]=WsT; pa.WT[2]=WtT; pa.WT[3]=WsvT; pa.WT[4]=WtvT;
    pa.bias[0]=bq; pa.bias[1]=bs; pa.bias[2]=bt; pa.bias[3]=bsv; pa.bias[4]=btv;
    pa.C[0]=gq;    pa.C[1]=gsk;  pa.C[2]=gtk;  pa.C[3]=gsv;   pa.C[4]=gtv;

    transpose_w   <<<dim3(8,24,6),  256>>>(tw);
    proj_mma      <<<dim3(4,48),    256, SMEM_MMA>>>(pa);
    transpose_vals<<<dim3(8,16,2),  256>>>(gsv, gtv, gsvT, gtvT);
    tri_mma       <<<dim3(32,16),   256, SMEM_MMA>>>(gq, gsk, gtk, gw);
    softmax_kernel<<<B_*L_,         256>>>(gw, grs);
    ctx_mma       <<<dim3(4,4,16),  256, SMEM_MMA>>>(gw, gsvT, gtvT, gpart);
    ctx_reduce    <<<1024,          256>>>(gpart, grs, gctx);
    out_mma       <<<dim3(4,16,3),  256, SMEM_MMA>>>(query, gctx, WoT, gpart);
    out_reduce    <<<1024,          256>>>(gpart, bo, out);
}

// round 7
// speedup vs baseline: 1.3328x; 1.3328x over previous
#include <cuda_runtime.h>
#include <math.h>

#define B_  16
#define L_  128
#define S_  64
#define T_  64
#define QD  1024
#define HD  512
#define OD  512
#define ST_ 4096

typedef unsigned long long u64;
typedef unsigned int u32;

// ---------------- scratch (static device globals) ---------------------------
__device__ float g_q  [B_*L_*HD];
__device__ float g_sk [B_*S_*HD];
__device__ float g_tk [B_*T_*HD];
__device__ float g_sv [B_*S_*HD];
__device__ float g_tv [B_*T_*HD];
__device__ float g_svT[B_*HD*S_];
__device__ float g_tvT[B_*HD*T_];
__device__ float g_w  [(size_t)B_*L_*ST_];       // 33.5 MB
__device__ float g_rs [B_*L_];
__device__ float g_ctx[B_*L_*HD];
__device__ float g_part[128*128*512];            // split-K scratch (33.5 MB)
__device__ float g_wT [5*512*1024 + 512*1536];   // transposed weights (13.6 MB)

// ---------------- small helpers ---------------------------------------------
__device__ __forceinline__ u32 tf32r(float x){
    u32 y; asm("cvt.rna.tf32.f32 %0, %1;":"=r"(y):"f"(x)); return y;
}
__device__ __forceinline__ float tf32f(float x){ return __uint_as_float(tf32r(x)); }
__device__ __forceinline__ u32 smem_u32(const void* p){
    u32 a; asm("{ .reg .u64 t; cvta.to.shared.u64 t, %1; cvt.u32.u64 %0, t; }":"=r"(a):"l"(p));
    return a;
}
__device__ __forceinline__ void mma8(float d[4], const u32 a[4], const u32 b[2]){
    asm volatile("mma.sync.aligned.m16n8k8.row.col.f32.tf32.tf32.f32 "
        "{%0,%1,%2,%3}, {%4,%5,%6,%7}, {%8,%9}, {%0,%1,%2,%3};"
        : "+f"(d[0]),"+f"(d[1]),"+f"(d[2]),"+f"(d[3])
        : "r"(a[0]),"r"(a[1]),"r"(a[2]),"r"(a[3]),"r"(b[0]),"r"(b[1]));
}
#define LDSM4(r0,r1,r2,r3,addr) \
    asm volatile("ldmatrix.sync.aligned.m8n8.x4.shared.b16 {%0,%1,%2,%3}, [%4];" \
        : "=r"(r0),"=r"(r1),"=r"(r2),"=r"(r3) : "r"(addr))
#define CPA16(dst,src) \
    asm volatile("cp.async.cg.shared.global [%0], [%1], 16;"::"r"(dst),"l"(src):"memory")
#define CPA_COMMIT() asm volatile("cp.async.commit_group;":::"memory")
#define CPA_WAIT0()  asm volatile("cp.async.wait_group 0;":::"memory")

// dynamic smem: A slots @ bytes 0,16384 ; B slots @ 32768,49152  (64 KB total)
#define SMEM_MMA 65536

// ---- shared mma-tile core pieces -------------------------------------------
#define MMA_PROLOG() \
    int tid=threadIdx.x, lane=tid&31, wid=tid>>5; \
    int wm = wid&3, wn = wid>>2; \
    int gid = lane>>2, tig = lane&3; \
    int l7 = lane&7, lq = lane>>3; \
    u32 smem_u = smem_u32(dsm); \
    int a_sh = lq>>1, b_sh = lq&1; \
    u32 a_row[2], b_row[4]; \
    _Pragma("unroll") \
    for (int mf=0;mf<2;mf++) a_row[mf] = (u32)(wm*32 + mf*16 + (lq&1)*8 + l7)*128u; \
    _Pragma("unroll") \
    for (int p=0;p<4;p++)    b_row[p]  = (u32)(wn*64 + (2*p + (lq>>1))*8 + l7)*128u; \
    int row_[4], seg_[4]; u32 stg_[4]; \
    _Pragma("unroll") \
    for (int j=0;j<4;j++){ int f4 = tid + j*256; row_[j]=f4>>3; seg_[j]=f4&7; \
        stg_[j] = (u32)(row_[j]*128 + ((seg_[j]^(row_[j]&7))<<4)); } \
    float acc[2][8][4]; \
    _Pragma("unroll") \
    for(int mf=0;mf<2;mf++) \
        _Pragma("unroll") \
        for(int nf=0;nf<8;nf++) \
            _Pragma("unroll") \
            for(int r=0;r<4;r++) acc[mf][nf][r]=0.f;

#define MMA_COMPUTE(slot) do { \
    u32 Ab_ = smem_u + (u32)(slot)*16384u; \
    u32 Bb_ = smem_u + 32768u + (u32)(slot)*16384u; \
    _Pragma("unroll") \
    for (int ks=0; ks<4; ks++){ \
        u32 asg = (u32)(((ks*2 + a_sh) ^ l7) << 4); \
        u32 bsg = (u32)(((ks*2 + b_sh) ^ l7) << 4); \
        u32 afr[2][4]; u32 bfr[8][2]; \
        _Pragma("unroll") \
        for (int mf=0;mf<2;mf++) \
            LDSM4(afr[mf][0],afr[mf][1],afr[mf][2],afr[mf][3], Ab_ + a_row[mf] + asg); \
        _Pragma("unroll") \
        for (int p=0;p<4;p++) \
            LDSM4(bfr[2*p][0],bfr[2*p][1],bfr[2*p+1][0],bfr[2*p+1][1], Bb_ + b_row[p] + bsg); \
        _Pragma("unroll") \
        for (int mf=0;mf<2;mf++) \
            _Pragma("unroll") \
            for (int nf=0;nf<8;nf++) mma8(acc[mf][nf], afr[mf], bfr[nf]); \
    } \
} while(0)

#define STS_B(slot, j, v4) \
    *(float4*)((char*)dsm + 32768 + (u32)(slot)*16384u + stg_[j]) = (v4)

// ============ trilinear logits via mma.sync: C[128l x 128st] = Q @ P^T ======
__global__ __launch_bounds__(256) void tri_mma(const float* __restrict__ q,
        const float* __restrict__ sk, const float* __restrict__ tk, float* __restrict__ w){
    extern __shared__ __align__(16) float dsm[];
    int tile = blockIdx.x, b = blockIdx.y;
    const float* qb  = q  + (size_t)b*L_*HD;
    MMA_PROLOG();
    // per-thread B-gen row pointers (fixed across k-tiles)
    const float* skp[4]; const float* tkp[4];
    #pragma unroll
    for (int j=0;j<4;j++){
        int st = tile*128 + row_[j];
        skp[j] = sk + (size_t)(b*S_ + (st>>6))*HD + seg_[j]*4;
        tkp[j] = tk + (size_t)(b*T_ + (st&63))*HD + seg_[j]*4;
    }
    const float* qp[4];
    #pragma unroll
    for (int j=0;j<4;j++) qp[j] = qb + (size_t)row_[j]*HD + seg_[j]*4;

    // prologue: tile 0
    #pragma unroll
    for (int j=0;j<4;j++) CPA16(smem_u + stg_[j], qp[j]);
    CPA_COMMIT();
    float4 pb[4];
    #pragma unroll
    for (int j=0;j<4;j++){
        float4 a = *(const float4*)(tkp[j]);
        float4 c = *(const float4*)(skp[j]);
        pb[j] = make_float4(a.x*c.x, a.y*c.y, a.z*c.z, a.w*c.w);
    }
    #pragma unroll
    for (int j=0;j<4;j++) STS_B(0, j, pb[j]);
    CPA_WAIT0();
    __syncthreads();

    const int NT = HD/32;   // 16
    for (int kt=0; kt<NT; kt++){
        int slot = kt&1;
        if (kt+1 < NT){
            int kc = (kt+1)*32;
            u32 nb = smem_u + (u32)(slot^1)*16384u;
            #pragma unroll
            for (int j=0;j<4;j++) CPA16(nb + stg_[j], qp[j] + kc);
            CPA_COMMIT();
            #pragma unroll
            for (int j=0;j<4;j++){
                float4 a = *(const float4*)(tkp[j] + kc);
                float4 c = *(const float4*)(skp[j] + kc);
                pb[j] = make_float4(a.x*c.x, a.y*c.y, a.z*c.z, a.w*c.w);
            }
        }
        MMA_COMPUTE(slot);
        if (kt+1 < NT){
            #pragma unroll
            for (int j=0;j<4;j++) STS_B(slot^1, j, pb[j]);
            CPA_WAIT0();
        }
        __syncthreads();
    }

    const float scale = 0.044194173824159216f;  // 1/sqrt(512)
    #pragma unroll
    for (int mf=0;mf<2;mf++){
        int row = wm*32 + mf*16 + gid;
        float* w0 = w + ((size_t)(b*L_+row))*ST_ + tile*128 + wn*64 + tig*2;
        #pragma unroll
        for (int nf=0;nf<8;nf++){
            *(float2*)(w0 + nf*8)          = make_float2(acc[mf][nf][0]*scale, acc[mf][nf][1]*scale);
            *(float2*)(w0 + nf*8 + 8*ST_)  = make_float2(acc[mf][nf][2]*scale, acc[mf][nf][3]*scale);
        }
    }
}

// ====== ctx via mma.sync: part[b,sp][128l x 128k] = E_chunk @ V^T ===========
__global__ __launch_bounds__(256) void ctx_mma(const float* __restrict__ E,
        const float* __restrict__ svT, const float* __restrict__ tvT, float* __restrict__ part){
    extern __shared__ __align__(16) float dsm[];
    int n0 = blockIdx.x*128, sp = blockIdx.y, b = blockIdx.z;
    const float* Eb  = E   + (size_t)b*L_*ST_ + sp*1024;
    const float* svb = svT + ((size_t)b*HD + n0)*S_;
    const float* tvb = tvT + ((size_t)b*HD + n0)*T_;
    MMA_PROLOG();
    const float* Ep[4];
    #pragma unroll
    for (int j=0;j<4;j++) Ep[j] = Eb + (size_t)row_[j]*ST_ + seg_[j]*4;

    // prologue: tile 0
    #pragma unroll
    for (int j=0;j<4;j++) CPA16(smem_u + stg_[j], Ep[j]);
    CPA_COMMIT();
    float4 pb[4];
    {   int st0 = sp*1024, s = st0>>6, tb = st0&63;
        #pragma unroll
        for (int j=0;j<4;j++){
            float4 t4 = *(const float4*)(tvb + (size_t)row_[j]*T_ + tb + seg_[j]*4);
            float sc = svb[(size_t)row_[j]*S_ + s];
            pb[j] = make_float4(t4.x*sc, t4.y*sc, t4.z*sc, t4.w*sc);
        }
    }
    #pragma unroll
    for (int j=0;j<4;j++) STS_B(0, j, pb[j]);
    CPA_WAIT0();
    __syncthreads();

    const int NT = 1024/32;  // 32
    for (int kt=0; kt<NT; kt++){
        int slot = kt&1;
        if (kt+1 < NT){
            int kc = (kt+1)*32;
            u32 nb = smem_u + (u32)(slot^1)*16384u;
            #pragma unroll
            for (int j=0;j<4;j++) CPA16(nb + stg_[j], Ep[j] + kc);
            CPA_COMMIT();
            int st0 = sp*1024 + kc, s = st0>>6, tb = st0&63;
            #pragma unroll
            for (int j=0;j<4;j++){
                float4 t4 = *(const float4*)(tvb + (size_t)row_[j]*T_ + tb + seg_[j]*4);
                float sc = svb[(size_t)row_[j]*S_ + s];
                pb[j] = make_float4(t4.x*sc, t4.y*sc, t4.z*sc, t4.w*sc);
            }
        }
        MMA_COMPUTE(slot);
        if (kt+1 < NT){
            #pragma unroll
            for (int j=0;j<4;j++) STS_B(slot^1, j, pb[j]);
            CPA_WAIT0();
        }
        __syncthreads();
    }

    #pragma unroll
    for (int mf=0;mf<2;mf++){
        int row = wm*32 + mf*16 + gid;
        float* p0 = part + ((size_t)(b*4+sp)*128 + row)*512 + n0 + wn*64 + tig*2;
        #pragma unroll
        for (int nf=0;nf<8;nf++){
            *(float2*)(p0 + nf*8)         = make_float2(acc[mf][nf][0], acc[mf][nf][1]);
            *(float2*)(p0 + nf*8 + 8*512) = make_float2(acc[mf][nf][2], acc[mf][nf][3]);
        }
    }
}

// ============ projections via mma.sync: C = A[Mx1024] @ W + bias ============
struct ProjArgs {
    const float* A[5];
    const float* WT[5];
    const float* bias[5];
    float*       C[5];
};

__global__ __launch_bounds__(256) void proj_mma(ProjArgs args){
    extern __shared__ __align__(16) float dsm[];
    int y = blockIdx.y;
    int task, mt;
    if (y < 16){ task=0; mt=y; } else { task = 1 + ((y-16)>>3); mt = (y-16)&7; }
    int bm = mt*128, bn = blockIdx.x*128;
    const float* Ab   = args.A[task]  + (size_t)bm*QD;
    const float* Bw   = args.WT[task] + (size_t)bn*QD;
    const float* bias = args.bias[task];
    float*       C    = args.C[task]  + (size_t)bm*OD + bn;
    MMA_PROLOG();
    const float* Ap[4]; const float* Bp[4];
    #pragma unroll
    for (int j=0;j<4;j++){
        Ap[j] = Ab + (size_t)row_[j]*QD + seg_[j]*4;
        Bp[j] = Bw + (size_t)row_[j]*QD + seg_[j]*4;
    }

    #pragma unroll
    for (int j=0;j<4;j++){ CPA16(smem_u + stg_[j], Ap[j]); CPA16(smem_u + 32768u + stg_[j], Bp[j]); }
    CPA_COMMIT();
    CPA_WAIT0();
    __syncthreads();

    const int NT = QD/32;  // 32
    for (int kt=0; kt<NT; kt++){
        int slot = kt&1;
        if (kt+1 < NT){
            int kc = (kt+1)*32;
            u32 nb = smem_u + (u32)(slot^1)*16384u;
            #pragma unroll
            for (int j=0;j<4;j++){ CPA16(nb + stg_[j], Ap[j] + kc); CPA16(nb + 32768u + stg_[j], Bp[j] + kc); }
            CPA_COMMIT();
        }
        MMA_COMPUTE(slot);
        if (kt+1 < NT) CPA_WAIT0();
        __syncthreads();
    }

    const float* bp = bias + bn + wn*64 + tig*2;
    #pragma unroll
    for (int mf=0;mf<2;mf++){
        int row = wm*32 + mf*16 + gid;
        float* c0 = C + (size_t)row*OD + wn*64 + tig*2;
        #pragma unroll
        for (int nf=0;nf<8;nf++){
            float b0 = bp[nf*8], b1 = bp[nf*8+1];
            *(float2*)(c0 + nf*8)        = make_float2(tf32f(acc[mf][nf][0]+b0), tf32f(acc[mf][nf][1]+b1));
            *(float2*)(c0 + nf*8 + 8*OD) = make_float2(tf32f(acc[mf][nf][2]+b0), tf32f(acc[mf][nf][3]+b1));
        }
    }
}

// ===== out partials via mma.sync: split-K = 3x512 over concat(query,ctx) ====
__global__ __launch_bounds__(256) void out_mma(const float* __restrict__ query,
        const float* __restrict__ ctx, const float* __restrict__ WoT, float* __restrict__ part){
    extern __shared__ __align__(16) float dsm[];
    int bn = blockIdx.x*128, bm = blockIdx.y*128, sp = blockIdx.z;
    const float* Ab; int lda;
    if (sp < 2){ Ab = query + (size_t)bm*QD + sp*512; lda = QD; }
    else       { Ab = ctx   + (size_t)bm*HD;          lda = HD; }
    const float* Bw = WoT + (size_t)bn*1536 + sp*512;
    MMA_PROLOG();
    const float* Ap[4]; const float* Bp[4];
    #pragma unroll
    for (int j=0;j<4;j++){
        Ap[j] = Ab + (size_t)row_[j]*lda + seg_[j]*4;
        Bp[j] = Bw + (size_t)row_[j]*1536 + seg_[j]*4;
    }

    #pragma unroll
    for (int j=0;j<4;j++){ CPA16(smem_u + stg_[j], Ap[j]); CPA16(smem_u + 32768u + stg_[j], Bp[j]); }
    CPA_COMMIT();
    CPA_WAIT0();
    __syncthreads();

    const int NT = 512/32;  // 16
    for (int kt=0; kt<NT; kt++){
        int slot = kt&1;
        if (kt+1 < NT){
            int kc = (kt+1)*32;
            u32 nb = smem_u + (u32)(slot^1)*16384u;
            #pragma unroll
            for (int j=0;j<4;j++){ CPA16(nb + stg_[j], Ap[j] + kc); CPA16(nb + 32768u + stg_[j], Bp[j] + kc); }
            CPA_COMMIT();
        }
        MMA_COMPUTE(slot);
        if (kt+1 < NT) CPA_WAIT0();
        __syncthreads();
    }

    #pragma unroll
    for (int mf=0;mf<2;mf++){
        int row = wm*32 + mf*16 + gid;
        float* p0 = part + ((size_t)sp*2048 + bm + row)*512 + bn + wn*64 + tig*2;
        #pragma unroll
        for (int nf=0;nf<8;nf++){
            *(float2*)(p0 + nf*8)         = make_float2(acc[mf][nf][0], acc[mf][nf][1]);
            *(float2*)(p0 + nf*8 + 8*512) = make_float2(acc[mf][nf][2], acc[mf][nf][3]);
        }
    }
}

// -------- transpose weights: WT[n][k] = tf32(W[k][n])  (N = 512 always) -----
struct TWArgs { const float* src[6]; float* dst[6]; int K[6]; };
__global__ void transpose_w(TWArgs a){
    __shared__ float tb[64][65];
    int mid = blockIdx.z;
    int K = a.K[mid];
    int k0 = blockIdx.y*64;
    if (k0 >= K) return;
    int n0 = blockIdx.x*64;
    const float* src = a.src[mid];
    float* dst = a.dst[mid];
    int tid = threadIdx.x;
    #pragma unroll
    for (int j=0;j<16;j++){
        int e = tid + j*256, kk = e>>6, nn = e&63;
        tb[nn][kk] = src[(size_t)(k0+kk)*512 + n0+nn];
    }
    __syncthreads();
    #pragma unroll
    for (int j=0;j<16;j++){
        int e = tid + j*256, nn = e>>6, kk = e&63;
        dst[(size_t)(n0+nn)*K + k0+kk] = tf32f(tb[nn][kk]);
    }
}

// -------- transpose sv/tv: vT[b][k][s] = v[b][s][k] ------------------------
__global__ void transpose_vals(const float* __restrict__ sv, const float* __restrict__ tv,
                               float* __restrict__ svT, float* __restrict__ tvT){
    __shared__ float tilebuf[64][65];
    int k0 = blockIdx.x*64, b = blockIdx.y;
    const float* src = blockIdx.z ? tv : sv;
    float* dst = blockIdx.z ? tvT : svT;
    int tid = threadIdx.x;
    #pragma unroll
    for (int j = 0; j < 16; j++){
        int e = tid + j*256, s = e>>6, k = e&63;
        tilebuf[k][s] = src[(size_t)(b*64 + s)*HD + k0 + k];
    }
    __syncthreads();
    #pragma unroll
    for (int j = 0; j < 16; j++){
        int e = tid + j*256, k = e>>6, s = e&63;
        dst[(size_t)(b*HD + k0 + k)*64 + s] = tilebuf[k][s];
    }
}

// ----------- joint softmax over st=4096; stores tf32(exp) + rowsum ----------
__global__ void softmax_kernel(float* __restrict__ w, float* __restrict__ rowsum) {
    int row = blockIdx.x;
    float4* p4 = (float4*)(w + (size_t)row * ST_);
    int tid = threadIdx.x;
    float4 v[4];
    float mx = -1e30f;
    #pragma unroll
    for (int i = 0; i < 4; i++) {
        v[i] = p4[tid + i*256];
        mx = fmaxf(mx, fmaxf(fmaxf(v[i].x, v[i].y), fmaxf(v[i].z, v[i].w)));
    }
    __shared__ float red[256];
    red[tid] = mx; __syncthreads();
    #pragma unroll
    for (int s = 128; s > 0; s >>= 1) {
        if (tid < s) red[tid] = fmaxf(red[tid], red[tid+s]);
        __syncthreads();
    }
    mx = red[0];
    __syncthreads();
    float sum = 0.f;
    #pragma unroll
    for (int i = 0; i < 4; i++) {
        float4 e;
        e.x = expf(v[i].x - mx); e.y = expf(v[i].y - mx);
        e.z = expf(v[i].z - mx); e.w = expf(v[i].w - mx);
        sum += (e.x + e.y) + (e.z + e.w);
        p4[tid + i*256] = make_float4(tf32f(e.x), tf32f(e.y), tf32f(e.z), tf32f(e.w));
    }
    red[tid] = sum; __syncthreads();
    #pragma unroll
    for (int s = 128; s > 0; s >>= 1) {
        if (tid < s) red[tid] += red[tid+s];
        __syncthreads();
    }
    if (tid == 0) rowsum[row] = red[0];
}

// reduce the 4 split-K partials, apply 1/rowsum, round to tf32 for out_mma
__global__ void ctx_reduce(const float* __restrict__ part, const float* __restrict__ rs,
                           float* __restrict__ ctx){
    int gid = blockIdx.x*256 + threadIdx.x;       // float4 id over 16*128*128
    int n4 = gid & 127; int rest = gid >> 7; int l = rest & 127; int b = rest >> 7;
    const float4* p = (const float4*)part;
    float4 a = make_float4(0,0,0,0);
    #pragma unroll
    for (int sp=0; sp<4; sp++){
        float4 v = p[ ((size_t)(b*4+sp)*128 + l)*128 + n4 ];
        a.x+=v.x; a.y+=v.y; a.z+=v.z; a.w+=v.w;
    }
    float inv = 1.f / rs[b*128 + l];
    ((float4*)ctx)[gid] = make_float4(tf32f(a.x*inv), tf32f(a.y*inv), tf32f(a.z*inv), tf32f(a.w*inv));
}

// reduce 3 split-K partials + bias + relu
__global__ void out_reduce(const float* __restrict__ part, const float* __restrict__ bo,
                           float* __restrict__ out){
    int gid = blockIdx.x*256 + threadIdx.x;       // float4 id over 2048*128
    int n4 = gid & 127; int m = gid >> 7;
    float4 p0 = ((const float4*)part)[(size_t)m*128 + n4];
    float4 p1 = ((const float4*)part)[(size_t)(2048+m)*128 + n4];
    float4 p2 = ((const float4*)part)[(size_t)(4096+m)*128 + n4];
    float4 bb = ((const float4*)bo)[n4];
    float4 o = make_float4(fmaxf(p0.x+p1.x+p2.x+bb.x, 0.f), fmaxf(p0.y+p1.y+p2.y+bb.y, 0.f),
                           fmaxf(p0.z+p1.z+p2.z+bb.z, 0.f), fmaxf(p0.w+p1.w+p2.w+bb.w, 0.f));
    ((float4*)out)[gid] = o;
}

// ----------------------------------------------------------------------------
extern "C" void kernel_launch(void* const* d_in, const int* in_sizes, int n_in,
                              void* d_out, int out_size) {
    const float* query = (const float*)d_in[0];
    const float* src   = (const float*)d_in[1];
    const float* trg   = (const float*)d_in[2];
    const float* Wq    = (const float*)d_in[3];
    const float* bq    = (const float*)d_in[4];
    const float* Ws    = (const float*)d_in[5];
    const float* bs    = (const float*)d_in[6];
    const float* Wt    = (const float*)d_in[7];
    const float* bt    = (const float*)d_in[8];
    const float* Wsv   = (const float*)d_in[9];
    const float* bsv   = (const float*)d_in[10];
    const float* Wtv   = (const float*)d_in[11];
    const float* btv   = (const float*)d_in[12];
    const float* Wo    = (const float*)d_in[13];
    const float* bo    = (const float*)d_in[14];
    float* out = (float*)d_out;

    float *gq, *gsk, *gtk, *gsv, *gtv, *gsvT, *gtvT, *gw, *grs, *gctx, *gpart, *gwT;
    cudaGetSymbolAddress((void**)&gq,   g_q);
    cudaGetSymbolAddress((void**)&gsk,  g_sk);
    cudaGetSymbolAddress((void**)&gtk,  g_tk);
    cudaGetSymbolAddress((void**)&gsv,  g_sv);
    cudaGetSymbolAddress((void**)&gtv,  g_tv);
    cudaGetSymbolAddress((void**)&gsvT, g_svT);
    cudaGetSymbolAddress((void**)&gtvT, g_tvT);
    cudaGetSymbolAddress((void**)&gw,   g_w);
    cudaGetSymbolAddress((void**)&grs,  g_rs);
    cudaGetSymbolAddress((void**)&gctx, g_ctx);
    cudaGetSymbolAddress((void**)&gpart,g_part);
    cudaGetSymbolAddress((void**)&gwT,  g_wT);

    static int smem_set = 0;
    if (!smem_set){
        cudaFuncSetAttribute(tri_mma,  cudaFuncAttributeMaxDynamicSharedMemorySize, SMEM_MMA);
        cudaFuncSetAttribute(ctx_mma,  cudaFuncAttributeMaxDynamicSharedMemorySize, SMEM_MMA);
        cudaFuncSetAttribute(proj_mma, cudaFuncAttributeMaxDynamicSharedMemorySize, SMEM_MMA);
        cudaFuncSetAttribute(out_mma,  cudaFuncAttributeMaxDynamicSharedMemorySize, SMEM_MMA);
        smem_set = 1;
    }

    float* WqT  = gwT;
    float* WsT  = gwT + 1*512*1024;
    float* WtT  = gwT + 2*512*1024;
    float* WsvT = gwT + 3*512*1024;
    float* WtvT = gwT + 4*512*1024;
    float* WoT  = gwT + 5*512*1024;

    TWArgs tw;
    tw.src[0]=Wq;  tw.dst[0]=WqT;  tw.K[0]=1024;
    tw.src[1]=Ws;  tw.dst[1]=WsT;  tw.K[1]=1024;
    tw.src[2]=Wt;  tw.dst[2]=WtT;  tw.K[2]=1024;
    tw.src[3]=Wsv; tw.dst[3]=WsvT; tw.K[3]=1024;
    tw.src[4]=Wtv; tw.dst[4]=WtvT; tw.K[4]=1024;
    tw.src[5]=Wo;  tw.dst[5]=WoT;  tw.K[5]=1536;

    ProjArgs pa;
    pa.A[0]=query; pa.A[1]=src;  pa.A[2]=trg;  pa.A[3]=src;   pa.A[4]=trg;
    pa.WT[0]=WqT;  pa.WT[1]=WsT; pa.WT[2]=WtT; pa.WT[3]=WsvT; pa.WT[4]=WtvT;
    pa.bias[0]=bq; pa.bias[1]=bs; pa.bias[2]=bt; pa.bias[3]=bsv; pa.bias[4]=btv;
    pa.C[0]=gq;    pa.C[1]=gsk;  pa.C[2]=gtk;  pa.C[3]=gsv;   pa.C[4]=gtv;

    transpose_w   <<<dim3(8,24,6),  256>>>(tw);
    proj_mma      <<<dim3(4,48),    256, SMEM_MMA>>>(pa);
    transpose_vals<<<dim3(8,16,2),  256>>>(gsv, gtv, gsvT, gtvT);
    tri_mma       <<<dim3(32,16),   256, SMEM_MMA>>>(gq, gsk, gtk, gw);
    softmax_kernel<<<B_*L_,         256>>>(gw, grs);
    ctx_mma       <<<dim3(4,4,16),  256, SMEM_MMA>>>(gw, gsvT, gtvT, gpart);
    ctx_reduce    <<<1024,          256>>>(gpart, grs, gctx);
    out_mma       <<<dim3(4,16,3),  256, SMEM_MMA>>>(query, gctx, WoT, gpart);
    out_reduce    <<<1024,          256>>>(gpart, bo, out);
}

// round 8
// speedup vs baseline: 1.4778x; 1.1089x over previous
#include <cuda_runtime.h>
#include <math.h>

#define B_  16
#define L_  128
#define S_  64
#define T_  64
#define QD  1024
#define HD  512
#define OD  512
#define ST_ 4096

typedef unsigned long long u64;
typedef unsigned int u32;

// ---------------- scratch (static device globals) ---------------------------
__device__ float g_q  [B_*L_*HD];
__device__ float g_sk [B_*S_*HD];
__device__ float g_tk [B_*T_*HD];
__device__ float g_sv [B_*S_*HD];
__device__ float g_tv [B_*T_*HD];
__device__ float g_svT[B_*HD*S_];
__device__ float g_tvT[B_*HD*T_];
__device__ float g_w  [(size_t)B_*L_*ST_];       // 33.5 MB
__device__ float g_rs [B_*L_];
__device__ float g_ctx[B_*L_*HD];
__device__ float g_part[128*128*512];            // split-K scratch (33.5 MB)
__device__ float g_wT [5*512*1024 + 512*1536];   // transposed weights (13.6 MB)

// ---------------- small helpers ---------------------------------------------
__device__ __forceinline__ u32 tf32r(float x){
    u32 y; asm("cvt.rna.tf32.f32 %0, %1;":"=r"(y):"f"(x)); return y;
}
__device__ __forceinline__ float tf32f(float x){ return __uint_as_float(tf32r(x)); }
__device__ __forceinline__ u32 smem_u32(const void* p){
    u32 a; asm("{ .reg .u64 t; cvta.to.shared.u64 t, %1; cvt.u32.u64 %0, t; }":"=r"(a):"l"(p));
    return a;
}
__device__ __forceinline__ void mma8(float d[4], const u32 a[4], const u32 b[2]){
    asm volatile("mma.sync.aligned.m16n8k8.row.col.f32.tf32.tf32.f32 "
        "{%0,%1,%2,%3}, {%4,%5,%6,%7}, {%8,%9}, {%0,%1,%2,%3};"
        : "+f"(d[0]),"+f"(d[1]),"+f"(d[2]),"+f"(d[3])
        : "r"(a[0]),"r"(a[1]),"r"(a[2]),"r"(a[3]),"r"(b[0]),"r"(b[1]));
}
#define LDSM4(r0,r1,r2,r3,addr) \
    asm volatile("ldmatrix.sync.aligned.m8n8.x4.shared.b16 {%0,%1,%2,%3}, [%4];" \
        : "=r"(r0),"=r"(r1),"=r"(r2),"=r"(r3) : "r"(addr))
#define CPA16(dst,src) \
    asm volatile("cp.async.cg.shared.global [%0], [%1], 16;"::"r"(dst),"l"(src):"memory")
#define CPA_COMMIT() asm volatile("cp.async.commit_group;":::"memory")
#define CPA_WAIT0()  asm volatile("cp.async.wait_group 0;":::"memory")

// dynamic smem: A slots @ bytes 0,16384 ; B slots @ 32768,49152  (64 KB total)
#define SMEM_MMA 65536

// ---- shared mma-tile core pieces -------------------------------------------
#define MMA_PROLOG() \
    int tid=threadIdx.x, lane=tid&31, wid=tid>>5; \
    int wm = wid&3, wn = wid>>2; \
    int gid = lane>>2, tig = lane&3; \
    int l7 = lane&7, lq = lane>>3; \
    u32 smem_u = smem_u32(dsm); \
    int a_sh = lq>>1, b_sh = lq&1; \
    u32 a_row[2], b_row[4]; \
    _Pragma("unroll") \
    for (int mf=0;mf<2;mf++) a_row[mf] = (u32)(wm*32 + mf*16 + (lq&1)*8 + l7)*128u; \
    _Pragma("unroll") \
    for (int p=0;p<4;p++)    b_row[p]  = (u32)(wn*64 + (2*p + (lq>>1))*8 + l7)*128u; \
    int row_[4], seg_[4]; u32 stg_[4]; \
    _Pragma("unroll") \
    for (int j=0;j<4;j++){ int f4 = tid + j*256; row_[j]=f4>>3; seg_[j]=f4&7; \
        stg_[j] = (u32)(row_[j]*128 + ((seg_[j]^(row_[j]&7))<<4)); } \
    float acc[2][8][4]; \
    _Pragma("unroll") \
    for(int mf=0;mf<2;mf++) \
        _Pragma("unroll") \
        for(int nf=0;nf<8;nf++) \
            _Pragma("unroll") \
            for(int r=0;r<4;r++) acc[mf][nf][r]=0.f;

#define MMA_COMPUTE(slot) do { \
    u32 Ab_ = smem_u + (u32)(slot)*16384u; \
    u32 Bb_ = smem_u + 32768u + (u32)(slot)*16384u; \
    _Pragma("unroll") \
    for (int ks=0; ks<4; ks++){ \
        u32 asg = (u32)(((ks*2 + a_sh) ^ l7) << 4); \
        u32 bsg = (u32)(((ks*2 + b_sh) ^ l7) << 4); \
        u32 afr[2][4]; u32 bfr[8][2]; \
        _Pragma("unroll") \
        for (int mf=0;mf<2;mf++) \
            LDSM4(afr[mf][0],afr[mf][1],afr[mf][2],afr[mf][3], Ab_ + a_row[mf] + asg); \
        _Pragma("unroll") \
        for (int p=0;p<4;p++) \
            LDSM4(bfr[2*p][0],bfr[2*p][1],bfr[2*p+1][0],bfr[2*p+1][1], Bb_ + b_row[p] + bsg); \
        _Pragma("unroll") \
        for (int mf=0;mf<2;mf++) \
            _Pragma("unroll") \
            for (int nf=0;nf<8;nf++) mma8(acc[mf][nf], afr[mf], bfr[nf]); \
    } \
} while(0)

#define STS_B(slot, j, v4) \
    *(float4*)((char*)dsm + 32768 + (u32)(slot)*16384u + stg_[j]) = (v4)

// ============ trilinear logits via mma.sync: C[128l x 128st] = Q @ P^T ======
__global__ __launch_bounds__(256,2) void tri_mma(const float* __restrict__ q,
        const float* __restrict__ sk, const float* __restrict__ tk, float* __restrict__ w){
    extern __shared__ __align__(16) float dsm[];
    int tile = blockIdx.x, b = blockIdx.y;
    const float* qb  = q  + (size_t)b*L_*HD;
    MMA_PROLOG();
    // per-thread B-gen row pointers (fixed across k-tiles)
    const float* skp[4]; const float* tkp[4];
    #pragma unroll
    for (int j=0;j<4;j++){
        int st = tile*128 + row_[j];
        skp[j] = sk + (size_t)(b*S_ + (st>>6))*HD + seg_[j]*4;
        tkp[j] = tk + (size_t)(b*T_ + (st&63))*HD + seg_[j]*4;
    }
    const float* qp[4];
    #pragma unroll
    for (int j=0;j<4;j++) qp[j] = qb + (size_t)row_[j]*HD + seg_[j]*4;

    // prologue: tile 0
    #pragma unroll
    for (int j=0;j<4;j++) CPA16(smem_u + stg_[j], qp[j]);
    CPA_COMMIT();
    float4 pb[4];
    #pragma unroll
    for (int j=0;j<4;j++){
        float4 a = *(const float4*)(tkp[j]);
        float4 c = *(const float4*)(skp[j]);
        pb[j] = make_float4(a.x*c.x, a.y*c.y, a.z*c.z, a.w*c.w);
    }
    #pragma unroll
    for (int j=0;j<4;j++) STS_B(0, j, pb[j]);
    CPA_WAIT0();
    __syncthreads();

    const int NT = HD/32;   // 16
    for (int kt=0; kt<NT; kt++){
        int slot = kt&1;
        if (kt+1 < NT){
            int kc = (kt+1)*32;
            u32 nb = smem_u + (u32)(slot^1)*16384u;
            #pragma unroll
            for (int j=0;j<4;j++) CPA16(nb + stg_[j], qp[j] + kc);
            CPA_COMMIT();
            #pragma unroll
            for (int j=0;j<4;j++){
                float4 a = *(const float4*)(tkp[j] + kc);
                float4 c = *(const float4*)(skp[j] + kc);
                pb[j] = make_float4(a.x*c.x, a.y*c.y, a.z*c.z, a.w*c.w);
            }
        }
        MMA_COMPUTE(slot);
        if (kt+1 < NT){
            #pragma unroll
            for (int j=0;j<4;j++) STS_B(slot^1, j, pb[j]);
            CPA_WAIT0();
        }
        __syncthreads();
    }

    const float scale = 0.044194173824159216f;  // 1/sqrt(512)
    #pragma unroll
    for (int mf=0;mf<2;mf++){
        int row = wm*32 + mf*16 + gid;
        float* w0 = w + ((size_t)(b*L_+row))*ST_ + tile*128 + wn*64 + tig*2;
        #pragma unroll
        for (int nf=0;nf<8;nf++){
            *(float2*)(w0 + nf*8)          = make_float2(acc[mf][nf][0]*scale, acc[mf][nf][1]*scale);
            *(float2*)(w0 + nf*8 + 8*ST_)  = make_float2(acc[mf][nf][2]*scale, acc[mf][nf][3]*scale);
        }
    }
}

// ====== ctx via mma.sync: part[b,sp][128l x 128k] = E_chunk @ V^T ===========
__global__ __launch_bounds__(256,2) void ctx_mma(const float* __restrict__ E,
        const float* __restrict__ svT, const float* __restrict__ tvT, float* __restrict__ part){
    extern __shared__ __align__(16) float dsm[];
    int n0 = blockIdx.x*128, sp = blockIdx.y, b = blockIdx.z;
    const float* Eb  = E   + (size_t)b*L_*ST_ + sp*1024;
    const float* svb = svT + ((size_t)b*HD + n0)*S_;
    const float* tvb = tvT + ((size_t)b*HD + n0)*T_;
    MMA_PROLOG();
    const float* Ep[4];
    #pragma unroll
    for (int j=0;j<4;j++) Ep[j] = Eb + (size_t)row_[j]*ST_ + seg_[j]*4;

    // prologue: tile 0
    #pragma unroll
    for (int j=0;j<4;j++) CPA16(smem_u + stg_[j], Ep[j]);
    CPA_COMMIT();
    float4 pb[4];
    {   int st0 = sp*1024, s = st0>>6, tb = st0&63;
        #pragma unroll
        for (int j=0;j<4;j++){
            float4 t4 = *(const float4*)(tvb + (size_t)row_[j]*T_ + tb + seg_[j]*4);
            float sc = svb[(size_t)row_[j]*S_ + s];
            pb[j] = make_float4(t4.x*sc, t4.y*sc, t4.z*sc, t4.w*sc);
        }
    }
    #pragma unroll
    for (int j=0;j<4;j++) STS_B(0, j, pb[j]);
    CPA_WAIT0();
    __syncthreads();

    const int NT = 1024/32;  // 32
    for (int kt=0; kt<NT; kt++){
        int slot = kt&1;
        if (kt+1 < NT){
            int kc = (kt+1)*32;
            u32 nb = smem_u + (u32)(slot^1)*16384u;
            #pragma unroll
            for (int j=0;j<4;j++) CPA16(nb + stg_[j], Ep[j] + kc);
            CPA_COMMIT();
            int st0 = sp*1024 + kc, s = st0>>6, tb = st0&63;
            #pragma unroll
            for (int j=0;j<4;j++){
                float4 t4 = *(const float4*)(tvb + (size_t)row_[j]*T_ + tb + seg_[j]*4);
                float sc = svb[(size_t)row_[j]*S_ + s];
                pb[j] = make_float4(t4.x*sc, t4.y*sc, t4.z*sc, t4.w*sc);
            }
        }
        MMA_COMPUTE(slot);
        if (kt+1 < NT){
            #pragma unroll
            for (int j=0;j<4;j++) STS_B(slot^1, j, pb[j]);
            CPA_WAIT0();
        }
        __syncthreads();
    }

    #pragma unroll
    for (int mf=0;mf<2;mf++){
        int row = wm*32 + mf*16 + gid;
        float* p0 = part + ((size_t)(b*4+sp)*128 + row)*512 + n0 + wn*64 + tig*2;
        #pragma unroll
        for (int nf=0;nf<8;nf++){
            *(float2*)(p0 + nf*8)         = make_float2(acc[mf][nf][0], acc[mf][nf][1]);
            *(float2*)(p0 + nf*8 + 8*512) = make_float2(acc[mf][nf][2], acc[mf][nf][3]);
        }
    }
}

// ============ projections via mma.sync: C = A[Mx1024] @ W + bias ============
struct ProjArgs {
    const float* A[5];
    const float* WT[5];
    const float* bias[5];
    float*       C[5];
};

__global__ __launch_bounds__(256,2) void proj_mma(ProjArgs args){
    extern __shared__ __align__(16) float dsm[];
    int y = blockIdx.y;
    int task, mt;
    if (y < 16){ task=0; mt=y; } else { task = 1 + ((y-16)>>3); mt = (y-16)&7; }
    int bm = mt*128, bn = blockIdx.x*128;
    const float* Ab   = args.A[task]  + (size_t)bm*QD;
    const float* Bw   = args.WT[task] + (size_t)bn*QD;
    const float* bias = args.bias[task];
    float*       C    = args.C[task]  + (size_t)bm*OD + bn;
    MMA_PROLOG();
    const float* Ap[4]; const float* Bp[4];
    #pragma unroll
    for (int j=0;j<4;j++){
        Ap[j] = Ab + (size_t)row_[j]*QD + seg_[j]*4;
        Bp[j] = Bw + (size_t)row_[j]*QD + seg_[j]*4;
    }

    #pragma unroll
    for (int j=0;j<4;j++){ CPA16(smem_u + stg_[j], Ap[j]); CPA16(smem_u + 32768u + stg_[j], Bp[j]); }
    CPA_COMMIT();
    CPA_WAIT0();
    __syncthreads();

    const int NT = QD/32;  // 32
    for (int kt=0; kt<NT; kt++){
        int slot = kt&1;
        if (kt+1 < NT){
            int kc = (kt+1)*32;
            u32 nb = smem_u + (u32)(slot^1)*16384u;
            #pragma unroll
            for (int j=0;j<4;j++){ CPA16(nb + stg_[j], Ap[j] + kc); CPA16(nb + 32768u + stg_[j], Bp[j] + kc); }
            CPA_COMMIT();
        }
        MMA_COMPUTE(slot);
        if (kt+1 < NT) CPA_WAIT0();
        __syncthreads();
    }

    const float* bp = bias + bn + wn*64 + tig*2;
    #pragma unroll
    for (int mf=0;mf<2;mf++){
        int row = wm*32 + mf*16 + gid;
        float* c0 = C + (size_t)row*OD + wn*64 + tig*2;
        #pragma unroll
        for (int nf=0;nf<8;nf++){
            float b0 = bp[nf*8], b1 = bp[nf*8+1];
            *(float2*)(c0 + nf*8)        = make_float2(tf32f(acc[mf][nf][0]+b0), tf32f(acc[mf][nf][1]+b1));
            *(float2*)(c0 + nf*8 + 8*OD) = make_float2(tf32f(acc[mf][nf][2]+b0), tf32f(acc[mf][nf][3]+b1));
        }
    }
}

// ===== out partials via mma.sync: split-K = 3x512 over concat(query,ctx) ====
__global__ __launch_bounds__(256,2) void out_mma(const float* __restrict__ query,
        const float* __restrict__ ctx, const float* __restrict__ WoT, float* __restrict__ part){
    extern __shared__ __align__(16) float dsm[];
    int bn = blockIdx.x*128, bm = blockIdx.y*128, sp = blockIdx.z;
    const float* Ab; int lda;
    if (sp < 2){ Ab = query + (size_t)bm*QD + sp*512; lda = QD; }
    else       { Ab = ctx   + (size_t)bm*HD;          lda = HD; }
    const float* Bw = WoT + (size_t)bn*1536 + sp*512;
    MMA_PROLOG();
    const float* Ap[4]; const float* Bp[4];
    #pragma unroll
    for (int j=0;j<4;j++){
        Ap[j] = Ab + (size_t)row_[j]*lda + seg_[j]*4;
        Bp[j] = Bw + (size_t)row_[j]*1536 + seg_[j]*4;
    }

    #pragma unroll
    for (int j=0;j<4;j++){ CPA16(smem_u + stg_[j], Ap[j]); CPA16(smem_u + 32768u + stg_[j], Bp[j]); }
    CPA_COMMIT();
    CPA_WAIT0();
    __syncthreads();

    const int NT = 512/32;  // 16
    for (int kt=0; kt<NT; kt++){
        int slot = kt&1;
        if (kt+1 < NT){
            int kc = (kt+1)*32;
            u32 nb = smem_u + (u32)(slot^1)*16384u;
            #pragma unroll
            for (int j=0;j<4;j++){ CPA16(nb + stg_[j], Ap[j] + kc); CPA16(nb + 32768u + stg_[j], Bp[j] + kc); }
            CPA_COMMIT();
        }
        MMA_COMPUTE(slot);
        if (kt+1 < NT) CPA_WAIT0();
        __syncthreads();
    }

    #pragma unroll
    for (int mf=0;mf<2;mf++){
        int row = wm*32 + mf*16 + gid;
        float* p0 = part + ((size_t)sp*2048 + bm + row)*512 + bn + wn*64 + tig*2;
        #pragma unroll
        for (int nf=0;nf<8;nf++){
            *(float2*)(p0 + nf*8)         = make_float2(acc[mf][nf][0], acc[mf][nf][1]);
            *(float2*)(p0 + nf*8 + 8*512) = make_float2(acc[mf][nf][2], acc[mf][nf][3]);
        }
    }
}

// -------- transpose weights: WT[n][k] = tf32(W[k][n])  (N = 512 always) -----
struct TWArgs { const float* src[6]; float* dst[6]; int K[6]; };
__global__ void transpose_w(TWArgs a){
    __shared__ float tb[64][65];
    int mid = blockIdx.z;
    int K = a.K[mid];
    int k0 = blockIdx.y*64;
    if (k0 >= K) return;
    int n0 = blockIdx.x*64;
    const float* src = a.src[mid];
    float* dst = a.dst[mid];
    int tid = threadIdx.x;
    #pragma unroll
    for (int j=0;j<16;j++){
        int e = tid + j*256, kk = e>>6, nn = e&63;
        tb[nn][kk] = src[(size_t)(k0+kk)*512 + n0+nn];
    }
    __syncthreads();
    #pragma unroll
    for (int j=0;j<16;j++){
        int e = tid + j*256, nn = e>>6, kk = e&63;
        dst[(size_t)(n0+nn)*K + k0+kk] = tf32f(tb[nn][kk]);
    }
}

// -------- transpose sv/tv: vT[b][k][s] = v[b][s][k] ------------------------
__global__ void transpose_vals(const float* __restrict__ sv, const float* __restrict__ tv,
                               float* __restrict__ svT, float* __restrict__ tvT){
    __shared__ float tilebuf[64][65];
    int k0 = blockIdx.x*64, b = blockIdx.y;
    const float* src = blockIdx.z ? tv : sv;
    float* dst = blockIdx.z ? tvT : svT;
    int tid = threadIdx.x;
    #pragma unroll
    for (int j = 0; j < 16; j++){
        int e = tid + j*256, s = e>>6, k = e&63;
        tilebuf[k][s] = src[(size_t)(b*64 + s)*HD + k0 + k];
    }
    __syncthreads();
    #pragma unroll
    for (int j = 0; j < 16; j++){
        int e = tid + j*256, k = e>>6, s = e&63;
        dst[(size_t)(b*HD + k0 + k)*64 + s] = tilebuf[k][s];
    }
}

// ----------- joint softmax over st=4096; stores tf32(exp) + rowsum ----------
__global__ void softmax_kernel(float* __restrict__ w, float* __restrict__ rowsum) {
    int row = blockIdx.x;
    float4* p4 = (float4*)(w + (size_t)row * ST_);
    int tid = threadIdx.x;
    float4 v[4];
    float mx = -1e30f;
    #pragma unroll
    for (int i = 0; i < 4; i++) {
        v[i] = p4[tid + i*256];
        mx = fmaxf(mx, fmaxf(fmaxf(v[i].x, v[i].y), fmaxf(v[i].z, v[i].w)));
    }
    __shared__ float red[256];
    red[tid] = mx; __syncthreads();
    #pragma unroll
    for (int s = 128; s > 0; s >>= 1) {
        if (tid < s) red[tid] = fmaxf(red[tid], red[tid+s]);
        __syncthreads();
    }
    mx = red[0];
    __syncthreads();
    float sum = 0.f;
    #pragma unroll
    for (int i = 0; i < 4; i++) {
        float4 e;
        e.x = expf(v[i].x - mx); e.y = expf(v[i].y - mx);
        e.z = expf(v[i].z - mx); e.w = expf(v[i].w - mx);
        sum += (e.x + e.y) + (e.z + e.w);
        p4[tid + i*256] = make_float4(tf32f(e.x), tf32f(e.y), tf32f(e.z), tf32f(e.w));
    }
    red[tid] = sum; __syncthreads();
    #pragma unroll
    for (int s = 128; s > 0; s >>= 1) {
        if (tid < s) red[tid] += red[tid+s];
        __syncthreads();
    }
    if (tid == 0) rowsum[row] = red[0];
}

// reduce the 4 split-K partials, apply 1/rowsum, round to tf32 for out_mma
__global__ void ctx_reduce(const float* __restrict__ part, const float* __restrict__ rs,
                           float* __restrict__ ctx){
    int gid = blockIdx.x*256 + threadIdx.x;       // float4 id over 16*128*128
    int n4 = gid & 127; int rest = gid >> 7; int l = rest & 127; int b = rest >> 7;
    const float4* p = (const float4*)part;
    float4 a = make_float4(0,0,0,0);
    #pragma unroll
    for (int sp=0; sp<4; sp++){
        float4 v = p[ ((size_t)(b*4+sp)*128 + l)*128 + n4 ];
        a.x+=v.x; a.y+=v.y; a.z+=v.z; a.w+=v.w;
    }
    float inv = 1.f / rs[b*128 + l];
    ((float4*)ctx)[gid] = make_float4(tf32f(a.x*inv), tf32f(a.y*inv), tf32f(a.z*inv), tf32f(a.w*inv));
}

// reduce 3 split-K partials + bias + relu
__global__ void out_reduce(const float* __restrict__ part, const float* __restrict__ bo,
                           float* __restrict__ out){
    int gid = blockIdx.x*256 + threadIdx.x;       // float4 id over 2048*128
    int n4 = gid & 127; int m = gid >> 7;
    float4 p0 = ((const float4*)part)[(size_t)m*128 + n4];
    float4 p1 = ((const float4*)part)[(size_t)(2048+m)*128 + n4];
    float4 p2 = ((const float4*)part)[(size_t)(4096+m)*128 + n4];
    float4 bb = ((const float4*)bo)[n4];
    float4 o = make_float4(fmaxf(p0.x+p1.x+p2.x+bb.x, 0.f), fmaxf(p0.y+p1.y+p2.y+bb.y, 0.f),
                           fmaxf(p0.z+p1.z+p2.z+bb.z, 0.f), fmaxf(p0.w+p1.w+p2.w+bb.w, 0.f));
    ((float4*)out)[gid] = o;
}

// ----------------------------------------------------------------------------
extern "C" void kernel_launch(void* const* d_in, const int* in_sizes, int n_in,
                              void* d_out, int out_size) {
    const float* query = (const float*)d_in[0];
    const float* src   = (const float*)d_in[1];
    const float* trg   = (const float*)d_in[2];
    const float* Wq    = (const float*)d_in[3];
    const float* bq    = (const float*)d_in[4];
    const float* Ws    = (const float*)d_in[5];
    const float* bs    = (const float*)d_in[6];
    const float* Wt    = (const float*)d_in[7];
    const float* bt    = (const float*)d_in[8];
    const float* Wsv   = (const float*)d_in[9];
    const float* bsv   = (const float*)d_in[10];
    const float* Wtv   = (const float*)d_in[11];
    const float* btv   = (const float*)d_in[12];
    const float* Wo    = (const float*)d_in[13];
    const float* bo    = (const float*)d_in[14];
    float* out = (float*)d_out;

    float *gq, *gsk, *gtk, *gsv, *gtv, *gsvT, *gtvT, *gw, *grs, *gctx, *gpart, *gwT;
    cudaGetSymbolAddress((void**)&gq,   g_q);
    cudaGetSymbolAddress((void**)&gsk,  g_sk);
    cudaGetSymbolAddress((void**)&gtk,  g_tk);
    cudaGetSymbolAddress((void**)&gsv,  g_sv);
    cudaGetSymbolAddress((void**)&gtv,  g_tv);
    cudaGetSymbolAddress((void**)&gsvT, g_svT);
    cudaGetSymbolAddress((void**)&gtvT, g_tvT);
    cudaGetSymbolAddress((void**)&gw,   g_w);
    cudaGetSymbolAddress((void**)&grs,  g_rs);
    cudaGetSymbolAddress((void**)&gctx, g_ctx);
    cudaGetSymbolAddress((void**)&gpart,g_part);
    cudaGetSymbolAddress((void**)&gwT,  g_wT);

    static int smem_set = 0;
    if (!smem_set){
        cudaFuncSetAttribute(tri_mma,  cudaFuncAttributeMaxDynamicSharedMemorySize, SMEM_MMA);
        cudaFuncSetAttribute(ctx_mma,  cudaFuncAttributeMaxDynamicSharedMemorySize, SMEM_MMA);
        cudaFuncSetAttribute(proj_mma, cudaFuncAttributeMaxDynamicSharedMemorySize, SMEM_MMA);
        cudaFuncSetAttribute(out_mma,  cudaFuncAttributeMaxDynamicSharedMemorySize, SMEM_MMA);
        smem_set = 1;
    }

    float* WqT  = gwT;
    float* WsT  = gwT + 1*512*1024;
    float* WtT  = gwT + 2*512*1024;
    float* WsvT = gwT + 3*512*1024;
    float* WtvT = gwT + 4*512*1024;
    float* WoT  = gwT + 5*512*1024;

    TWArgs tw;
    tw.src[0]=Wq;  tw.dst[0]=WqT;  tw.K[0]=1024;
    tw.src[1]=Ws;  tw.dst[1]=WsT;  tw.K[1]=1024;
    tw.src[2]=Wt;  tw.dst[2]=WtT;  tw.K[2]=1024;
    tw.src[3]=Wsv; tw.dst[3]=WsvT; tw.K[3]=1024;
    tw.src[4]=Wtv; tw.dst[4]=WtvT; tw.K[4]=1024;
    tw.src[5]=Wo;  tw.dst[5]=WoT;  tw.K[5]=1536;

    ProjArgs pa;
    pa.A[0]=query; pa.A[1]=src;  pa.A[2]=trg;  pa.A[3]=src;   pa.A[4]=trg;
    pa.WT[0]=WqT;  pa.WT[1]=WsT; pa.WT[2]=WtT; pa.WT[3]=WsvT; pa.WT[4]=WtvT;
    pa.bias[0]=bq; pa.bias[1]=bs; pa.bias[2]=bt; pa.bias[3]=bsv; pa.bias[4]=btv;
    pa.C[0]=gq;    pa.C[1]=gsk;  pa.C[2]=gtk;  pa.C[3]=gsv;   pa.C[4]=gtv;

    transpose_w   <<<dim3(8,24,6),  256>>>(tw);
    proj_mma      <<<dim3(4,48),    256, SMEM_MMA>>>(pa);
    transpose_vals<<<dim3(8,16,2),  256>>>(gsv, gtv, gsvT, gtvT);
    tri_mma       <<<dim3(32,16),   256, SMEM_MMA>>>(gq, gsk, gtk, gw);
    softmax_kernel<<<B_*L_,         256>>>(gw, grs);
    ctx_mma       <<<dim3(4,4,16),  256, SMEM_MMA>>>(gw, gsvT, gtvT, gpart);
    ctx_reduce    <<<1024,          256>>>(gpart, grs, gctx);
    out_mma       <<<dim3(4,16,3),  256, SMEM_MMA>>>(query, gctx, WoT, gpart);
    out_reduce    <<<1024,          256>>>(gpart, bo, out);
}

// round 9
// speedup vs baseline: 2.2765x; 1.5404x over previous
#include <cuda_runtime.h>
#include <cuda_fp16.h>
#include <math.h>

#define B_  16
#define L_  128
#define S_  64
#define T_  64
#define QD  1024
#define HD  512
#define OD  512
#define ST_ 4096

typedef unsigned long long u64;
typedef unsigned int u32;

// ---------------- scratch (static device globals) ---------------------------
__device__ __half g_qryh[B_*L_*QD];              // half(query)
__device__ __half g_srch[B_*S_*QD];
__device__ __half g_trgh[B_*T_*QD];
__device__ __half g_qh  [B_*L_*HD];
__device__ __half g_skh [B_*S_*HD];
__device__ __half g_tkh [B_*T_*HD];
__device__ __half g_svh [B_*S_*HD];
__device__ __half g_tvh [B_*T_*HD];
__device__ __half g_svTh[B_*HD*S_];
__device__ __half g_tvTh[B_*HD*T_];
__device__ float  g_w   [(size_t)B_*L_*ST_];     // fp32 logits (33.5 MB)
__device__ __half g_wh  [(size_t)B_*L_*ST_];     // half(exp) (16.8 MB)
__device__ float  g_rs  [B_*L_];
__device__ __half g_ctxh[B_*L_*HD];
__device__ float  g_part[128*128*512];           // split-K scratch fp32
__device__ __half g_wTh [5*512*1024 + 512*1536]; // half transposed weights

// ---------------- small helpers ---------------------------------------------
__device__ __forceinline__ u32 smem_u32(const void* p){
    u32 a; asm("{ .reg .u64 t; cvta.to.shared.u64 t, %1; cvt.u32.u64 %0, t; }":"=r"(a):"l"(p));
    return a;
}
__device__ __forceinline__ void mma16(float d[4], const u32 a[4], const u32 b[2]){
    asm volatile("mma.sync.aligned.m16n8k16.row.col.f32.f16.f16.f32 "
        "{%0,%1,%2,%3}, {%4,%5,%6,%7}, {%8,%9}, {%0,%1,%2,%3};"
        : "+f"(d[0]),"+f"(d[1]),"+f"(d[2]),"+f"(d[3])
        : "r"(a[0]),"r"(a[1]),"r"(a[2]),"r"(a[3]),"r"(b[0]),"r"(b[1]));
}
#define LDSM4(r0,r1,r2,r3,addr) \
    asm volatile("ldmatrix.sync.aligned.m8n8.x4.shared.b16 {%0,%1,%2,%3}, [%4];" \
        : "=r"(r0),"=r"(r1),"=r"(r2),"=r"(r3) : "r"(addr))
#define CPA16(dst,src) \
    asm volatile("cp.async.cg.shared.global [%0], [%1], 16;"::"r"(dst),"l"(src):"memory")
#define CPA_COMMIT() asm volatile("cp.async.commit_group;":::"memory")
#define CPA_WAIT0()  asm volatile("cp.async.wait_group 0;":::"memory")

__device__ __forceinline__ uint4 hmul16(uint4 a, uint4 b){
    __half2* pa=(__half2*)&a; __half2* pb=(__half2*)&b;
    uint4 r; __half2* pr=(__half2*)&r;
    pr[0]=__hmul2(pa[0],pb[0]); pr[1]=__hmul2(pa[1],pb[1]);
    pr[2]=__hmul2(pa[2],pb[2]); pr[3]=__hmul2(pa[3],pb[3]);
    return r;
}
__device__ __forceinline__ uint4 hscale16(uint4 a, __half sc){
    __half2 s2 = __half2half2(sc);
    __half2* pa=(__half2*)&a;
    uint4 r; __half2* pr=(__half2*)&r;
    pr[0]=__hmul2(pa[0],s2); pr[1]=__hmul2(pa[1],s2);
    pr[2]=__hmul2(pa[2],s2); pr[3]=__hmul2(pa[3],s2);
    return r;
}

// dynamic smem: A slots @ bytes 0,16384 ; B slots @ 32768,49152  (64 KB total)
// tile = 128 rows x 64 halfs (128 B/row), 8 segs of 16 B per row
#define SMEM_MMA 65536

#define MMA_PROLOG() \
    int tid=threadIdx.x, lane=tid&31, wid=tid>>5; \
    int wm = wid&3, wn = wid>>2; \
    int gid = lane>>2, tig = lane&3; \
    int l7 = lane&7, lq = lane>>3; \
    u32 smem_u = smem_u32(dsm); \
    int a_sh = lq>>1, b_sh = lq&1; \
    u32 a_row[2], b_row[4]; \
    _Pragma("unroll") \
    for (int mf=0;mf<2;mf++) a_row[mf] = (u32)(wm*32 + mf*16 + (lq&1)*8 + l7)*128u; \
    _Pragma("unroll") \
    for (int p=0;p<4;p++)    b_row[p]  = (u32)(wn*64 + (2*p + (lq>>1))*8 + l7)*128u; \
    int row_[4], seg_[4]; u32 stg_[4]; \
    _Pragma("unroll") \
    for (int j=0;j<4;j++){ int f4 = tid + j*256; row_[j]=f4>>3; seg_[j]=f4&7; \
        stg_[j] = (u32)(row_[j]*128 + ((seg_[j]^(row_[j]&7))<<4)); } \
    float acc[2][8][4]; \
    _Pragma("unroll") \
    for(int mf=0;mf<2;mf++) \
        _Pragma("unroll") \
        for(int nf=0;nf<8;nf++) \
            _Pragma("unroll") \
            for(int r=0;r<4;r++) acc[mf][nf][r]=0.f;

#define MMA_COMPUTE(slot) do { \
    u32 Ab_ = smem_u + (u32)(slot)*16384u; \
    u32 Bb_ = smem_u + 32768u + (u32)(slot)*16384u; \
    _Pragma("unroll") \
    for (int ks=0; ks<4; ks++){ \
        u32 asg = (u32)(((ks*2 + a_sh) ^ l7) << 4); \
        u32 bsg = (u32)(((ks*2 + b_sh) ^ l7) << 4); \
        u32 afr[2][4]; u32 bfr[8][2]; \
        _Pragma("unroll") \
        for (int mf=0;mf<2;mf++) \
            LDSM4(afr[mf][0],afr[mf][1],afr[mf][2],afr[mf][3], Ab_ + a_row[mf] + asg); \
        _Pragma("unroll") \
        for (int p=0;p<4;p++) \
            LDSM4(bfr[2*p][0],bfr[2*p][1],bfr[2*p+1][0],bfr[2*p+1][1], Bb_ + b_row[p] + bsg); \
        _Pragma("unroll") \
        for (int mf=0;mf<2;mf++) \
            _Pragma("unroll") \
            for (int nf=0;nf<8;nf++) mma16(acc[mf][nf], afr[mf], bfr[nf]); \
    } \
} while(0)

#define STS_B(slot, j, v4) \
    *(uint4*)((char*)dsm + 32768 + (u32)(slot)*16384u + stg_[j]) = (v4)

// ============ trilinear logits: C[128l x 128st] = Q @ (sk.*tk)^T ============
__global__ __launch_bounds__(256,2) void tri_mma(const __half* __restrict__ q,
        const __half* __restrict__ sk, const __half* __restrict__ tk, float* __restrict__ w){
    extern __shared__ __align__(16) float dsm[];
    int tile = blockIdx.x, b = blockIdx.y;
    const __half* qb = q + (size_t)b*L_*HD;
    MMA_PROLOG();
    const __half* skp[4]; const __half* tkp[4]; const __half* qp[4];
    #pragma unroll
    for (int j=0;j<4;j++){
        int st = tile*128 + row_[j];
        skp[j] = sk + (size_t)(b*S_ + (st>>6))*HD + seg_[j]*8;
        tkp[j] = tk + (size_t)(b*T_ + (st&63))*HD + seg_[j]*8;
        qp[j]  = qb + (size_t)row_[j]*HD + seg_[j]*8;
    }

    #pragma unroll
    for (int j=0;j<4;j++) CPA16(smem_u + stg_[j], qp[j]);
    CPA_COMMIT();
    uint4 pb[4];
    #pragma unroll
    for (int j=0;j<4;j++)
        pb[j] = hmul16(*(const uint4*)tkp[j], *(const uint4*)skp[j]);
    #pragma unroll
    for (int j=0;j<4;j++) STS_B(0, j, pb[j]);
    CPA_WAIT0();
    __syncthreads();

    const int NT = HD/64;   // 8
    for (int kt=0; kt<NT; kt++){
        int slot = kt&1;
        if (kt+1 < NT){
            int kc = (kt+1)*64;
            u32 nb = smem_u + (u32)(slot^1)*16384u;
            #pragma unroll
            for (int j=0;j<4;j++) CPA16(nb + stg_[j], qp[j] + kc);
            CPA_COMMIT();
            #pragma unroll
            for (int j=0;j<4;j++)
                pb[j] = hmul16(*(const uint4*)(tkp[j]+kc), *(const uint4*)(skp[j]+kc));
        }
        MMA_COMPUTE(slot);
        if (kt+1 < NT){
            #pragma unroll
            for (int j=0;j<4;j++) STS_B(slot^1, j, pb[j]);
            CPA_WAIT0();
        }
        __syncthreads();
    }

    const float scale = 0.044194173824159216f;  // 1/sqrt(512)
    #pragma unroll
    for (int mf=0;mf<2;mf++){
        int row = wm*32 + mf*16 + gid;
        float* w0 = w + ((size_t)(b*L_+row))*ST_ + tile*128 + wn*64 + tig*2;
        #pragma unroll
        for (int nf=0;nf<8;nf++){
            *(float2*)(w0 + nf*8)          = make_float2(acc[mf][nf][0]*scale, acc[mf][nf][1]*scale);
            *(float2*)(w0 + nf*8 + 8*ST_)  = make_float2(acc[mf][nf][2]*scale, acc[mf][nf][3]*scale);
        }
    }
}

// ====== ctx: part[b,sp][128l x 128k] = E_chunk @ (svT.*tvT)^T ===============
__global__ __launch_bounds__(256,2) void ctx_mma(const __half* __restrict__ E,
        const __half* __restrict__ svT, const __half* __restrict__ tvT, float* __restrict__ part){
    extern __shared__ __align__(16) float dsm[];
    int n0 = blockIdx.x*128, sp = blockIdx.y, b = blockIdx.z;
    const __half* Eb  = E   + (size_t)b*L_*ST_ + sp*1024;
    const __half* svb = svT + ((size_t)b*HD + n0)*S_;
    const __half* tvb = tvT + ((size_t)b*HD + n0)*T_;
    MMA_PROLOG();
    const __half* Ep[4];
    #pragma unroll
    for (int j=0;j<4;j++) Ep[j] = Eb + (size_t)row_[j]*ST_ + seg_[j]*8;

    #pragma unroll
    for (int j=0;j<4;j++) CPA16(smem_u + stg_[j], Ep[j]);
    CPA_COMMIT();
    uint4 pb[4];
    {   int s = sp*16;   // st-chunk of 64 = exactly one s (T=64), tb=0
        #pragma unroll
        for (int j=0;j<4;j++){
            uint4 t4 = *(const uint4*)(tvb + (size_t)row_[j]*T_ + seg_[j]*8);
            pb[j] = hscale16(t4, svb[(size_t)row_[j]*S_ + s]);
        }
    }
    #pragma unroll
    for (int j=0;j<4;j++) STS_B(0, j, pb[j]);
    CPA_WAIT0();
    __syncthreads();

    const int NT = 1024/64;  // 16
    for (int kt=0; kt<NT; kt++){
        int slot = kt&1;
        if (kt+1 < NT){
            int kc = (kt+1)*64;
            u32 nb = smem_u + (u32)(slot^1)*16384u;
            #pragma unroll
            for (int j=0;j<4;j++) CPA16(nb + stg_[j], Ep[j] + kc);
            CPA_COMMIT();
            int s = sp*16 + kt + 1;
            #pragma unroll
            for (int j=0;j<4;j++){
                uint4 t4 = *(const uint4*)(tvb + (size_t)row_[j]*T_ + seg_[j]*8);
                pb[j] = hscale16(t4, svb[(size_t)row_[j]*S_ + s]);
            }
        }
        MMA_COMPUTE(slot);
        if (kt+1 < NT){
            #pragma unroll
            for (int j=0;j<4;j++) STS_B(slot^1, j, pb[j]);
            CPA_WAIT0();
        }
        __syncthreads();
    }

    #pragma unroll
    for (int mf=0;mf<2;mf++){
        int row = wm*32 + mf*16 + gid;
        float* p0 = part + ((size_t)(b*4+sp)*128 + row)*512 + n0 + wn*64 + tig*2;
        #pragma unroll
        for (int nf=0;nf<8;nf++){
            *(float2*)(p0 + nf*8)         = make_float2(acc[mf][nf][0], acc[mf][nf][1]);
            *(float2*)(p0 + nf*8 + 8*512) = make_float2(acc[mf][nf][2], acc[mf][nf][3]);
        }
    }
}

// ============ projections: C = A[Mx1024] @ W + bias (half out) ==============
struct ProjArgs {
    const __half* A[5];
    const __half* WT[5];
    const float*  bias[5];
    __half*       C[5];
};

__global__ __launch_bounds__(256,2) void proj_mma(ProjArgs args){
    extern __shared__ __align__(16) float dsm[];
    int y = blockIdx.y;
    int task, mt;
    if (y < 16){ task=0; mt=y; } else { task = 1 + ((y-16)>>3); mt = (y-16)&7; }
    int bm = mt*128, bn = blockIdx.x*128;
    const __half* Ab   = args.A[task]  + (size_t)bm*QD;
    const __half* Bw   = args.WT[task] + (size_t)bn*QD;
    const float*  bias = args.bias[task];
    __half*       C    = args.C[task]  + (size_t)bm*OD + bn;
    MMA_PROLOG();
    const __half* Ap[4]; const __half* Bp[4];
    #pragma unroll
    for (int j=0;j<4;j++){
        Ap[j] = Ab + (size_t)row_[j]*QD + seg_[j]*8;
        Bp[j] = Bw + (size_t)row_[j]*QD + seg_[j]*8;
    }

    #pragma unroll
    for (int j=0;j<4;j++){ CPA16(smem_u + stg_[j], Ap[j]); CPA16(smem_u + 32768u + stg_[j], Bp[j]); }
    CPA_COMMIT();
    CPA_WAIT0();
    __syncthreads();

    const int NT = QD/64;  // 16
    for (int kt=0; kt<NT; kt++){
        int slot = kt&1;
        if (kt+1 < NT){
            int kc = (kt+1)*64;
            u32 nb = smem_u + (u32)(slot^1)*16384u;
            #pragma unroll
            for (int j=0;j<4;j++){ CPA16(nb + stg_[j], Ap[j] + kc); CPA16(nb + 32768u + stg_[j], Bp[j] + kc); }
            CPA_COMMIT();
        }
        MMA_COMPUTE(slot);
        if (kt+1 < NT) CPA_WAIT0();
        __syncthreads();
    }

    const float* bp = bias + bn + wn*64 + tig*2;
    #pragma unroll
    for (int mf=0;mf<2;mf++){
        int row = wm*32 + mf*16 + gid;
        __half* c0 = C + (size_t)row*OD + wn*64 + tig*2;
        #pragma unroll
        for (int nf=0;nf<8;nf++){
            float b0 = bp[nf*8], b1 = bp[nf*8+1];
            *(__half2*)(c0 + nf*8)        = __floats2half2_rn(acc[mf][nf][0]+b0, acc[mf][nf][1]+b1);
            *(__half2*)(c0 + nf*8 + 8*OD) = __floats2half2_rn(acc[mf][nf][2]+b0, acc[mf][nf][3]+b1);
        }
    }
}

// ===== out partials: split-K = 3x512 over concat(query,ctx) =================
__global__ __launch_bounds__(256,2) void out_mma(const __half* __restrict__ query,
        const __half* __restrict__ ctx, const __half* __restrict__ WoT, float* __restrict__ part){
    extern __shared__ __align__(16) float dsm[];
    int bn = blockIdx.x*128, bm = blockIdx.y*128, sp = blockIdx.z;
    const __half* Ab; int lda;
    if (sp < 2){ Ab = query + (size_t)bm*QD + sp*512; lda = QD; }
    else       { Ab = ctx   + (size_t)bm*HD;          lda = HD; }
    const __half* Bw = WoT + (size_t)bn*1536 + sp*512;
    MMA_PROLOG();
    const __half* Ap[4]; const __half* Bp[4];
    #pragma unroll
    for (int j=0;j<4;j++){
        Ap[j] = Ab + (size_t)row_[j]*lda + seg_[j]*8;
        Bp[j] = Bw + (size_t)row_[j]*1536 + seg_[j]*8;
    }

    #pragma unroll
    for (int j=0;j<4;j++){ CPA16(smem_u + stg_[j], Ap[j]); CPA16(smem_u + 32768u + stg_[j], Bp[j]); }
    CPA_COMMIT();
    CPA_WAIT0();
    __syncthreads();

    const int NT = 512/64;  // 8
    for (int kt=0; kt<NT; kt++){
        int slot = kt&1;
        if (kt+1 < NT){
            int kc = (kt+1)*64;
            u32 nb = smem_u + (u32)(slot^1)*16384u;
            #pragma unroll
            for (int j=0;j<4;j++){ CPA16(nb + stg_[j], Ap[j] + kc); CPA16(nb + 32768u + stg_[j], Bp[j] + kc); }
            CPA_COMMIT();
        }
        MMA_COMPUTE(slot);
        if (kt+1 < NT) CPA_WAIT0();
        __syncthreads();
    }

    #pragma unroll
    for (int mf=0;mf<2;mf++){
        int row = wm*32 + mf*16 + gid;
        float* p0 = part + ((size_t)sp*2048 + bm + row)*512 + bn + wn*64 + tig*2;
        #pragma unroll
        for (int nf=0;nf<8;nf++){
            *(float2*)(p0 + nf*8)         = make_float2(acc[mf][nf][0], acc[mf][nf][1]);
            *(float2*)(p0 + nf*8 + 8*512) = make_float2(acc[mf][nf][2], acc[mf][nf][3]);
        }
    }
}

// -------- convert fp32 inputs to half ---------------------------------------
__global__ void cvt_inputs(const float4* __restrict__ q, const float4* __restrict__ s,
                           const float4* __restrict__ t, uint2* __restrict__ qh,
                           uint2* __restrict__ sh, uint2* __restrict__ th){
    int gid = blockIdx.x*256 + threadIdx.x;   // over 1048576 float4s
    const float4* src; uint2* dst; int off;
    if (gid < 524288){ src=q; dst=qh; off=gid; }
    else if (gid < 786432){ src=s; dst=sh; off=gid-524288; }
    else { src=t; dst=th; off=gid-786432; }
    float4 v = src[off];
    uint2 r; __half2* pr=(__half2*)&r;
    pr[0]=__floats2half2_rn(v.x,v.y); pr[1]=__floats2half2_rn(v.z,v.w);
    dst[off]=r;
}

// -------- transpose weights: WT[n][k] = half(W[k][n]) -----------------------
struct TWArgs { const float* src[6]; __half* dst[6]; int K[6]; };
__global__ void transpose_w(TWArgs a){
    __shared__ float tb[64][65];
    int mid = blockIdx.z;
    int K = a.K[mid];
    int k0 = blockIdx.y*64;
    if (k0 >= K) return;
    int n0 = blockIdx.x*64;
    const float* src = a.src[mid];
    __half* dst = a.dst[mid];
    int tid = threadIdx.x;
    #pragma unroll
    for (int j=0;j<16;j++){
        int e = tid + j*256, kk = e>>6, nn = e&63;
        tb[nn][kk] = src[(size_t)(k0+kk)*512 + n0+nn];
    }
    __syncthreads();
    #pragma unroll
    for (int j=0;j<16;j++){
        int e = tid + j*256, nn = e>>6, kk = e&63;
        dst[(size_t)(n0+nn)*K + k0+kk] = __float2half(tb[nn][kk]);
    }
}

// -------- transpose sv/tv (half): vT[b][k][s] = v[b][s][k] ------------------
__global__ void transpose_vals(const __half* __restrict__ sv, const __half* __restrict__ tv,
                               __half* __restrict__ svT, __half* __restrict__ tvT){
    __shared__ __half tilebuf[64][65];
    int k0 = blockIdx.x*64, b = blockIdx.y;
    const __half* src = blockIdx.z ? tv : sv;
    __half* dst = blockIdx.z ? tvT : svT;
    int tid = threadIdx.x;
    #pragma unroll
    for (int j = 0; j < 16; j++){
        int e = tid + j*256, s = e>>6, k = e&63;
        tilebuf[k][s] = src[(size_t)(b*64 + s)*HD + k0 + k];
    }
    __syncthreads();
    #pragma unroll
    for (int j = 0; j < 16; j++){
        int e = tid + j*256, k = e>>6, s = e&63;
        dst[(size_t)(b*HD + k0 + k)*64 + s] = tilebuf[k][s];
    }
}

// ----------- joint softmax over st=4096; stores half(exp) + rowsum ----------
__global__ void softmax_kernel(const float* __restrict__ w, __half* __restrict__ wh,
                               float* __restrict__ rowsum) {
    int row = blockIdx.x;
    const float4* p4 = (const float4*)(w + (size_t)row * ST_);
    uint2* ph = (uint2*)(wh + (size_t)row * ST_);
    int tid = threadIdx.x;
    float4 v[4];
    float mx = -1e30f;
    #pragma unroll
    for (int i = 0; i < 4; i++) {
        v[i] = p4[tid + i*256];
        mx = fmaxf(mx, fmaxf(fmaxf(v[i].x, v[i].y), fmaxf(v[i].z, v[i].w)));
    }
    __shared__ float red[256];
    red[tid] = mx; __syncthreads();
    #pragma unroll
    for (int s = 128; s > 0; s >>= 1) {
        if (tid < s) red[tid] = fmaxf(red[tid], red[tid+s]);
        __syncthreads();
    }
    mx = red[0];
    __syncthreads();
    float sum = 0.f;
    #pragma unroll
    for (int i = 0; i < 4; i++) {
        float4 e;
        e.x = expf(v[i].x - mx); e.y = expf(v[i].y - mx);
        e.z = expf(v[i].z - mx); e.w = expf(v[i].w - mx);
        sum += (e.x + e.y) + (e.z + e.w);
        uint2 r; __half2* pr=(__half2*)&r;
        pr[0]=__floats2half2_rn(e.x,e.y); pr[1]=__floats2half2_rn(e.z,e.w);
        ph[tid + i*256] = r;
    }
    red[tid] = sum; __syncthreads();
    #pragma unroll
    for (int s = 128; s > 0; s >>= 1) {
        if (tid < s) red[tid] += red[tid+s];
        __syncthreads();
    }
    if (tid == 0) rowsum[row] = red[0];
}

// reduce the 4 split-K partials, apply 1/rowsum, emit half ctx
__global__ void ctx_reduce(const float* __restrict__ part, const float* __restrict__ rs,
                           __half* __restrict__ ctx){
    int gid = blockIdx.x*256 + threadIdx.x;       // 4-elem id over 16*128*128
    int n4 = gid & 127; int rest = gid >> 7; int l = rest & 127; int b = rest >> 7;
    const float4* p = (const float4*)part;
    float4 a = make_float4(0,0,0,0);
    #pragma unroll
    for (int sp=0; sp<4; sp++){
        float4 v = p[ ((size_t)(b*4+sp)*128 + l)*128 + n4 ];
        a.x+=v.x; a.y+=v.y; a.z+=v.z; a.w+=v.w;
    }
    float inv = 1.f / rs[b*128 + l];
    uint2 r; __half2* pr=(__half2*)&r;
    pr[0]=__floats2half2_rn(a.x*inv, a.y*inv); pr[1]=__floats2half2_rn(a.z*inv, a.w*inv);
    ((uint2*)ctx)[gid] = r;
}

// reduce 3 split-K partials + bias + relu
__global__ void out_reduce(const float* __restrict__ part, const float* __restrict__ bo,
                           float* __restrict__ out){
    int gid = blockIdx.x*256 + threadIdx.x;       // float4 id over 2048*128
    int n4 = gid & 127; int m = gid >> 7;
    float4 p0 = ((const float4*)part)[(size_t)m*128 + n4];
    float4 p1 = ((const float4*)part)[(size_t)(2048+m)*128 + n4];
    float4 p2 = ((const float4*)part)[(size_t)(4096+m)*128 + n4];
    float4 bb = ((const float4*)bo)[n4];
    float4 o = make_float4(fmaxf(p0.x+p1.x+p2.x+bb.x, 0.f), fmaxf(p0.y+p1.y+p2.y+bb.y, 0.f),
                           fmaxf(p0.z+p1.z+p2.z+bb.z, 0.f), fmaxf(p0.w+p1.w+p2.w+bb.w, 0.f));
    ((float4*)out)[gid] = o;
}

// ----------------------------------------------------------------------------
extern "C" void kernel_launch(void* const* d_in, const int* in_sizes, int n_in,
                              void* d_out, int out_size) {
    const float* query = (const float*)d_in[0];
    const float* src   = (const float*)d_in[1];
    const float* trg   = (const float*)d_in[2];
    const float* Wq    = (const float*)d_in[3];
    const float* bq    = (const float*)d_in[4];
    const float* Ws    = (const float*)d_in[5];
    const float* bs    = (const float*)d_in[6];
    const float* Wt    = (const float*)d_in[7];
    const float* bt    = (const float*)d_in[8];
    const float* Wsv   = (const float*)d_in[9];
    const float* bsv   = (const float*)d_in[10];
    const float* Wtv   = (const float*)d_in[11];
    const float* btv   = (const float*)d_in[12];
    const float* Wo    = (const float*)d_in[13];
    const float* bo    = (const float*)d_in[14];
    float* out = (float*)d_out;

    __half *qryh,*srch,*trgh,*qh,*skh,*tkh,*svh,*tvh,*svTh,*tvTh,*wh,*ctxh,*wTh;
    float *gw,*grs,*gpart;
    cudaGetSymbolAddress((void**)&qryh, g_qryh);
    cudaGetSymbolAddress((void**)&srch, g_srch);
    cudaGetSymbolAddress((void**)&trgh, g_trgh);
    cudaGetSymbolAddress((void**)&qh,   g_qh);
    cudaGetSymbolAddress((void**)&skh,  g_skh);
    cudaGetSymbolAddress((void**)&tkh,  g_tkh);
    cudaGetSymbolAddress((void**)&svh,  g_svh);
    cudaGetSymbolAddress((void**)&tvh,  g_tvh);
    cudaGetSymbolAddress((void**)&svTh, g_svTh);
    cudaGetSymbolAddress((void**)&tvTh, g_tvTh);
    cudaGetSymbolAddress((void**)&wh,   g_wh);
    cudaGetSymbolAddress((void**)&ctxh, g_ctxh);
    cudaGetSymbolAddress((void**)&wTh,  g_wTh);
    cudaGetSymbolAddress((void**)&gw,   g_w);
    cudaGetSymbolAddress((void**)&grs,  g_rs);
    cudaGetSymbolAddress((void**)&gpart,g_part);

    static int smem_set = 0;
    if (!smem_set){
        cudaFuncSetAttribute(tri_mma,  cudaFuncAttributeMaxDynamicSharedMemorySize, SMEM_MMA);
        cudaFuncSetAttribute(ctx_mma,  cudaFuncAttributeMaxDynamicSharedMemorySize, SMEM_MMA);
        cudaFuncSetAttribute(proj_mma, cudaFuncAttributeMaxDynamicSharedMemorySize, SMEM_MMA);
        cudaFuncSetAttribute(out_mma,  cudaFuncAttributeMaxDynamicSharedMemorySize, SMEM_MMA);
        smem_set = 1;
    }

    __half* WqT  = wTh;
    __half* WsT  = wTh + 1*512*1024;
    __half* WtT  = wTh + 2*512*1024;
    __half* WsvT = wTh + 3*512*1024;
    __half* WtvT = wTh + 4*512*1024;
    __half* WoT  = wTh + 5*512*1024;

    TWArgs tw;
    tw.src[0]=Wq;  tw.dst[0]=WqT;  tw.K[0]=1024;
    tw.src[1]=Ws;  tw.dst[1]=WsT;  tw.K[1]=1024;
    tw.src[2]=Wt;  tw.dst[2]=WtT;  tw.K[2]=1024;
    tw.src[3]=Wsv; tw.dst[3]=WsvT; tw.K[3]=1024;
    tw.src[4]=Wtv; tw.dst[4]=WtvT; tw.K[4]=1024;
    tw.src[5]=Wo;  tw.dst[5]=WoT;  tw.K[5]=1536;

    ProjArgs pa;
    pa.A[0]=qryh;  pa.A[1]=srch; pa.A[2]=trgh; pa.A[3]=srch;  pa.A[4]=trgh;
    pa.WT[0]=WqT;  pa.WT[1]=WsT; pa.WT[2]=WtT; pa.WT[3]=WsvT; pa.WT[4]=WtvT;
    pa.bias[0]=bq; pa.bias[1]=bs; pa.bias[2]=bt; pa.bias[3]=bsv; pa.bias[4]=btv;
    pa.C[0]=qh;    pa.C[1]=skh;  pa.C[2]=tkh;  pa.C[3]=svh;   pa.C[4]=tvh;

    cvt_inputs    <<<4096,          256>>>((const float4*)query, (const float4*)src,
                                           (const float4*)trg, (uint2*)qryh,
                                           (uint2*)srch, (uint2*)trgh);
    transpose_w   <<<dim3(8,24,6),  256>>>(tw);
    proj_mma      <<<dim3(4,48),    256, SMEM_MMA>>>(pa);
    transpose_vals<<<dim3(8,16,2),  256>>>(svh, tvh, svTh, tvTh);
    tri_mma       <<<dim3(32,16),   256, SMEM_MMA>>>(qh, skh, tkh, gw);
    softmax_kernel<<<B_*L_,         256>>>(gw, wh, grs);
    ctx_mma       <<<dim3(4,4,16),  256, SMEM_MMA>>>(wh, svTh, tvTh, gpart);
    ctx_reduce    <<<1024,          256>>>(gpart, grs, ctxh);
    out_mma       <<<dim3(4,16,3),  256, SMEM_MMA>>>(qryh, ctxh, WoT, gpart);
    out_reduce    <<<1024,          256>>>(gpart, bo, out);
}

// round 10
// speedup vs baseline: 2.5637x; 1.1261x over previous
#include <cuda_runtime.h>
#include <cuda_fp16.h>
#include <math.h>

#define B_  16
#define L_  128
#define S_  64
#define T_  64
#define QD  1024
#define HD  512
#define OD  512
#define ST_ 4096

typedef unsigned long long u64;
typedef unsigned int u32;

// ---------------- scratch (static device globals) ---------------------------
__device__ __half g_qryh[B_*L_*QD];
__device__ __half g_srch[B_*S_*QD];
__device__ __half g_trgh[B_*T_*QD];
__device__ __half g_qh  [B_*L_*HD];
__device__ __half g_skh [B_*S_*HD];
__device__ __half g_tkh [B_*T_*HD];
__device__ __half g_svh [B_*S_*HD];
__device__ __half g_tvh [B_*T_*HD];
__device__ __half g_svTh[B_*HD*S_];
__device__ __half g_tvTh[B_*HD*T_];
__device__ __half g_wl  [(size_t)B_*L_*ST_];     // half logits (16.8 MB)
__device__ __half g_wh  [(size_t)B_*L_*ST_];     // half exp    (16.8 MB)
__device__ float  g_rs  [B_*L_];
__device__ __half g_ctxh[B_*L_*HD];
__device__ __half g_parth[64*128*512];           // ctx split-K partials (half)
__device__ float  g_part[3*2048*512];            // out split-K partials (fp32)
__device__ __half g_wTh [5*512*1024 + 512*1536]; // half transposed weights

// ---------------- small helpers ---------------------------------------------
__device__ __forceinline__ u32 smem_u32(const void* p){
    u32 a; asm("{ .reg .u64 t; cvta.to.shared.u64 t, %1; cvt.u32.u64 %0, t; }":"=r"(a):"l"(p));
    return a;
}
__device__ __forceinline__ void mma16(float d[4], const u32 a[4], const u32 b[2]){
    asm volatile("mma.sync.aligned.m16n8k16.row.col.f32.f16.f16.f32 "
        "{%0,%1,%2,%3}, {%4,%5,%6,%7}, {%8,%9}, {%0,%1,%2,%3};"
        : "+f"(d[0]),"+f"(d[1]),"+f"(d[2]),"+f"(d[3])
        : "r"(a[0]),"r"(a[1]),"r"(a[2]),"r"(a[3]),"r"(b[0]),"r"(b[1]));
}
#define LDSM4(r0,r1,r2,r3,addr) \
    asm volatile("ldmatrix.sync.aligned.m8n8.x4.shared.b16 {%0,%1,%2,%3}, [%4];" \
        : "=r"(r0),"=r"(r1),"=r"(r2),"=r"(r3) : "r"(addr))
#define CPA16(dst,src) \
    asm volatile("cp.async.cg.shared.global [%0], [%1], 16;"::"r"(dst),"l"(src):"memory")
#define CPA_COMMIT() asm volatile("cp.async.commit_group;":::"memory")
#define CPA_WAIT0()  asm volatile("cp.async.wait_group 0;":::"memory")

__device__ __forceinline__ uint4 hmul16(uint4 a, uint4 b){
    __half2* pa=(__half2*)&a; __half2* pb=(__half2*)&b;
    uint4 r; __half2* pr=(__half2*)&r;
    pr[0]=__hmul2(pa[0],pb[0]); pr[1]=__hmul2(pa[1],pb[1]);
    pr[2]=__hmul2(pa[2],pb[2]); pr[3]=__hmul2(pa[3],pb[3]);
    return r;
}
__device__ __forceinline__ uint4 hscale16(uint4 a, __half sc){
    __half2 s2 = __half2half2(sc);
    __half2* pa=(__half2*)&a;
    uint4 r; __half2* pr=(__half2*)&r;
    pr[0]=__hmul2(pa[0],s2); pr[1]=__hmul2(pa[1],s2);
    pr[2]=__hmul2(pa[2],s2); pr[3]=__hmul2(pa[3],s2);
    return r;
}

#define SMEM_MMA 65536

#define MMA_PROLOG() \
    int tid=threadIdx.x, lane=tid&31, wid=tid>>5; \
    int wm = wid&3, wn = wid>>2; \
    int gid = lane>>2, tig = lane&3; \
    int l7 = lane&7, lq = lane>>3; \
    u32 smem_u = smem_u32(dsm); \
    int a_sh = lq>>1, b_sh = lq&1; \
    u32 a_row[2], b_row[4]; \
    _Pragma("unroll") \
    for (int mf=0;mf<2;mf++) a_row[mf] = (u32)(wm*32 + mf*16 + (lq&1)*8 + l7)*128u; \
    _Pragma("unroll") \
    for (int p=0;p<4;p++)    b_row[p]  = (u32)(wn*64 + (2*p + (lq>>1))*8 + l7)*128u; \
    int row_[4], seg_[4]; u32 stg_[4]; \
    _Pragma("unroll") \
    for (int j=0;j<4;j++){ int f4 = tid + j*256; row_[j]=f4>>3; seg_[j]=f4&7; \
        stg_[j] = (u32)(row_[j]*128 + ((seg_[j]^(row_[j]&7))<<4)); } \
    float acc[2][8][4]; \
    _Pragma("unroll") \
    for(int mf=0;mf<2;mf++) \
        _Pragma("unroll") \
        for(int nf=0;nf<8;nf++) \
            _Pragma("unroll") \
            for(int r=0;r<4;r++) acc[mf][nf][r]=0.f;

#define MMA_COMPUTE(slot) do { \
    u32 Ab_ = smem_u + (u32)(slot)*16384u; \
    u32 Bb_ = smem_u + 32768u + (u32)(slot)*16384u; \
    _Pragma("unroll") \
    for (int ks=0; ks<4; ks++){ \
        u32 asg = (u32)(((ks*2 + a_sh) ^ l7) << 4); \
        u32 bsg = (u32)(((ks*2 + b_sh) ^ l7) << 4); \
        u32 afr[2][4]; u32 bfr[8][2]; \
        _Pragma("unroll") \
        for (int mf=0;mf<2;mf++) \
            LDSM4(afr[mf][0],afr[mf][1],afr[mf][2],afr[mf][3], Ab_ + a_row[mf] + asg); \
        _Pragma("unroll") \
        for (int p=0;p<4;p++) \
            LDSM4(bfr[2*p][0],bfr[2*p][1],bfr[2*p+1][0],bfr[2*p+1][1], Bb_ + b_row[p] + bsg); \
        _Pragma("unroll") \
        for (int mf=0;mf<2;mf++) \
            _Pragma("unroll") \
            for (int nf=0;nf<8;nf++) mma16(acc[mf][nf], afr[mf], bfr[nf]); \
    } \
} while(0)

#define STS_B(slot, j, v4) \
    *(uint4*)((char*)dsm + 32768 + (u32)(slot)*16384u + stg_[j]) = (v4)

// ============ tri body: C[128l x 128st] = Q @ (sk.*tk)^T -> half logits =====
__device__ __forceinline__ void tri_body(const __half* __restrict__ q,
        const __half* __restrict__ sk, const __half* __restrict__ tk,
        __half* __restrict__ w, int tile, int b, float* dsm){
    const __half* qb = q + (size_t)b*L_*HD;
    MMA_PROLOG();
    const __half* skp[4]; const __half* tkp[4]; const __half* qp[4];
    #pragma unroll
    for (int j=0;j<4;j++){
        int st = tile*128 + row_[j];
        skp[j] = sk + (size_t)(b*S_ + (st>>6))*HD + seg_[j]*8;
        tkp[j] = tk + (size_t)(b*T_ + (st&63))*HD + seg_[j]*8;
        qp[j]  = qb + (size_t)row_[j]*HD + seg_[j]*8;
    }
    #pragma unroll
    for (int j=0;j<4;j++) CPA16(smem_u + stg_[j], qp[j]);
    CPA_COMMIT();
    uint4 pb[4];
    #pragma unroll
    for (int j=0;j<4;j++)
        pb[j] = hmul16(*(const uint4*)tkp[j], *(const uint4*)skp[j]);
    #pragma unroll
    for (int j=0;j<4;j++) STS_B(0, j, pb[j]);
    CPA_WAIT0();
    __syncthreads();

    const int NT = HD/64;   // 8
    for (int kt=0; kt<NT; kt++){
        int slot = kt&1;
        if (kt+1 < NT){
            int kc = (kt+1)*64;
            u32 nb = smem_u + (u32)(slot^1)*16384u;
            #pragma unroll
            for (int j=0;j<4;j++) CPA16(nb + stg_[j], qp[j] + kc);
            CPA_COMMIT();
            #pragma unroll
            for (int j=0;j<4;j++)
                pb[j] = hmul16(*(const uint4*)(tkp[j]+kc), *(const uint4*)(skp[j]+kc));
        }
        MMA_COMPUTE(slot);
        if (kt+1 < NT){
            #pragma unroll
            for (int j=0;j<4;j++) STS_B(slot^1, j, pb[j]);
            CPA_WAIT0();
        }
        __syncthreads();
    }

    const float scale = 0.044194173824159216f;
    #pragma unroll
    for (int mf=0;mf<2;mf++){
        int row = wm*32 + mf*16 + gid;
        __half* w0 = w + ((size_t)(b*L_+row))*ST_ + tile*128 + wn*64 + tig*2;
        #pragma unroll
        for (int nf=0;nf<8;nf++){
            *(__half2*)(w0 + nf*8)          = __floats2half2_rn(acc[mf][nf][0]*scale, acc[mf][nf][1]*scale);
            *(__half2*)(w0 + nf*8 + 8*ST_)  = __floats2half2_rn(acc[mf][nf][2]*scale, acc[mf][nf][3]*scale);
        }
    }
}

// ====== ctx body: parth[b,sp][128l x 128k] = E_chunk @ (svT.*tvT)^T =========
__device__ __forceinline__ void ctx_body(const __half* __restrict__ E,
        const __half* __restrict__ svT, const __half* __restrict__ tvT,
        __half* __restrict__ part, int nt, int sp, int b, float* dsm){
    int n0 = nt*128;
    const __half* Eb  = E   + (size_t)b*L_*ST_ + sp*1024;
    const __half* svb = svT + ((size_t)b*HD + n0)*S_;
    const __half* tvb = tvT + ((size_t)b*HD + n0)*T_;
    MMA_PROLOG();
    const __half* Ep[4];
    #pragma unroll
    for (int j=0;j<4;j++) Ep[j] = Eb + (size_t)row_[j]*ST_ + seg_[j]*8;

    #pragma unroll
    for (int j=0;j<4;j++) CPA16(smem_u + stg_[j], Ep[j]);
    CPA_COMMIT();
    uint4 pb[4];
    {   int s = sp*16;
        #pragma unroll
        for (int j=0;j<4;j++){
            uint4 t4 = *(const uint4*)(tvb + (size_t)row_[j]*T_ + seg_[j]*8);
            pb[j] = hscale16(t4, svb[(size_t)row_[j]*S_ + s]);
        }
    }
    #pragma unroll
    for (int j=0;j<4;j++) STS_B(0, j, pb[j]);
    CPA_WAIT0();
    __syncthreads();

    const int NT = 1024/64;  // 16
    for (int kt=0; kt<NT; kt++){
        int slot = kt&1;
        if (kt+1 < NT){
            int kc = (kt+1)*64;
            u32 nb = smem_u + (u32)(slot^1)*16384u;
            #pragma unroll
            for (int j=0;j<4;j++) CPA16(nb + stg_[j], Ep[j] + kc);
            CPA_COMMIT();
            int s = sp*16 + kt + 1;
            #pragma unroll
            for (int j=0;j<4;j++){
                uint4 t4 = *(const uint4*)(tvb + (size_t)row_[j]*T_ + seg_[j]*8);
                pb[j] = hscale16(t4, svb[(size_t)row_[j]*S_ + s]);
            }
        }
        MMA_COMPUTE(slot);
        if (kt+1 < NT){
            #pragma unroll
            for (int j=0;j<4;j++) STS_B(slot^1, j, pb[j]);
            CPA_WAIT0();
        }
        __syncthreads();
    }

    #pragma unroll
    for (int mf=0;mf<2;mf++){
        int row = wm*32 + mf*16 + gid;
        __half* p0 = part + ((size_t)(b*4+sp)*128 + row)*512 + n0 + wn*64 + tig*2;
        #pragma unroll
        for (int nf=0;nf<8;nf++){
            *(__half2*)(p0 + nf*8)         = __floats2half2_rn(acc[mf][nf][0], acc[mf][nf][1]);
            *(__half2*)(p0 + nf*8 + 8*512) = __floats2half2_rn(acc[mf][nf][2], acc[mf][nf][3]);
        }
    }
}

// ===== out body: fp32 partials, split-K 3x512 over concat(query,ctx) ========
__device__ __forceinline__ void out_body(const __half* __restrict__ query,
        const __half* __restrict__ ctx, const __half* __restrict__ WoT,
        float* __restrict__ part, int bnI, int bmI, int sp, float* dsm){
    int bn = bnI*128, bm = bmI*128;
    const __half* Ab; int lda;
    if (sp < 2){ Ab = query + (size_t)bm*QD + sp*512; lda = QD; }
    else       { Ab = ctx   + (size_t)bm*HD;          lda = HD; }
    const __half* Bw = WoT + (size_t)bn*1536 + sp*512;
    MMA_PROLOG();
    const __half* Ap[4]; const __half* Bp[4];
    #pragma unroll
    for (int j=0;j<4;j++){
        Ap[j] = Ab + (size_t)row_[j]*lda + seg_[j]*8;
        Bp[j] = Bw + (size_t)row_[j]*1536 + seg_[j]*8;
    }
    #pragma unroll
    for (int j=0;j<4;j++){ CPA16(smem_u + stg_[j], Ap[j]); CPA16(smem_u + 32768u + stg_[j], Bp[j]); }
    CPA_COMMIT();
    CPA_WAIT0();
    __syncthreads();

    const int NT = 512/64;  // 8
    for (int kt=0; kt<NT; kt++){
        int slot = kt&1;
        if (kt+1 < NT){
            int kc = (kt+1)*64;
            u32 nb = smem_u + (u32)(slot^1)*16384u;
            #pragma unroll
            for (int j=0;j<4;j++){ CPA16(nb + stg_[j], Ap[j] + kc); CPA16(nb + 32768u + stg_[j], Bp[j] + kc); }
            CPA_COMMIT();
        }
        MMA_COMPUTE(slot);
        if (kt+1 < NT) CPA_WAIT0();
        __syncthreads();
    }

    #pragma unroll
    for (int mf=0;mf<2;mf++){
        int row = wm*32 + mf*16 + gid;
        float* p0 = part + ((size_t)sp*2048 + bm + row)*512 + bn + wn*64 + tig*2;
        #pragma unroll
        for (int nf=0;nf<8;nf++){
            *(float2*)(p0 + nf*8)         = make_float2(acc[mf][nf][0], acc[mf][nf][1]);
            *(float2*)(p0 + nf*8 + 8*512) = make_float2(acc[mf][nf][2], acc[mf][nf][3]);
        }
    }
}

// -------- transpose_vals body (uses dynamic smem) ---------------------------
__device__ __forceinline__ void tvals_body(const __half* __restrict__ sv,
        const __half* __restrict__ tv, __half* __restrict__ svT, __half* __restrict__ tvT,
        int k0t, int b, int z, float* dsm){
    __half (*tilebuf)[65] = ( __half(*)[65] )dsm;
    int k0 = k0t*64;
    const __half* src = z ? tv : sv;
    __half* dst = z ? tvT : svT;
    int tid = threadIdx.x;
    #pragma unroll
    for (int j = 0; j < 16; j++){
        int e = tid + j*256, s = e>>6, k = e&63;
        tilebuf[k][s] = src[(size_t)(b*64 + s)*HD + k0 + k];
    }
    __syncthreads();
    #pragma unroll
    for (int j = 0; j < 16; j++){
        int e = tid + j*256, k = e>>6, s = e&63;
        dst[(size_t)(b*HD + k0 + k)*64 + s] = tilebuf[k][s];
    }
}

// ============ merged launch 3: tri (512 blocks) + transpose_vals (256) ======
__global__ __launch_bounds__(256,2) void l3_kernel(const __half* __restrict__ q,
        const __half* __restrict__ sk, const __half* __restrict__ tk,
        __half* __restrict__ w, const __half* __restrict__ sv,
        const __half* __restrict__ tv, __half* __restrict__ svT, __half* __restrict__ tvT){
    extern __shared__ __align__(16) float dsm[];
    int bx = blockIdx.x;
    if (bx < 512){
        tri_body(q, sk, tk, w, bx & 31, bx >> 5, dsm);
    } else {
        int local = bx - 512;
        tvals_body(sv, tv, svT, tvT, local & 7, (local >> 3) & 15, local >> 7, dsm);
    }
}

// ============ merged launch 5: ctx (256 blocks) + out sp0,1 (128) ===========
__global__ __launch_bounds__(256,2) void l5_kernel(const __half* __restrict__ E,
        const __half* __restrict__ svT, const __half* __restrict__ tvT,
        __half* __restrict__ cpart, const __half* __restrict__ query,
        const __half* __restrict__ WoT, float* __restrict__ opart){
    extern __shared__ __align__(16) float dsm[];
    int bx = blockIdx.x;
    if (bx < 256){
        int nt = bx & 3, sp = (bx >> 2) & 3, b = bx >> 4;
        ctx_body(E, svT, tvT, cpart, nt, sp, b, dsm);
    } else {
        int local = bx - 256;
        out_body(query, (const __half*)0, WoT, opart, local & 3, (local >> 2) & 15, local >> 6, dsm);
    }
}

// ============ out sp=2 (needs ctx) ==========================================
__global__ __launch_bounds__(256,2) void out_sp2_kernel(const __half* __restrict__ query,
        const __half* __restrict__ ctx, const __half* __restrict__ WoT, float* __restrict__ opart){
    extern __shared__ __align__(16) float dsm[];
    out_body(query, ctx, WoT, opart, blockIdx.x, blockIdx.y, 2, dsm);
}

// ============ projections: C = A[Mx1024] @ W + bias (half out) ==============
struct ProjArgs {
    const __half* A[5];
    const __half* WT[5];
    const float*  bias[5];
    __half*       C[5];
};

__global__ __launch_bounds__(256,2) void proj_mma(ProjArgs args){
    extern __shared__ __align__(16) float dsm[];
    int y = blockIdx.y;
    int task, mt;
    if (y < 16){ task=0; mt=y; } else { task = 1 + ((y-16)>>3); mt = (y-16)&7; }
    int bm = mt*128, bn = blockIdx.x*128;
    const __half* Ab   = args.A[task]  + (size_t)bm*QD;
    const __half* Bw   = args.WT[task] + (size_t)bn*QD;
    const float*  bias = args.bias[task];
    __half*       C    = args.C[task]  + (size_t)bm*OD + bn;
    MMA_PROLOG();
    const __half* Ap[4]; const __half* Bp[4];
    #pragma unroll
    for (int j=0;j<4;j++){
        Ap[j] = Ab + (size_t)row_[j]*QD + seg_[j]*8;
        Bp[j] = Bw + (size_t)row_[j]*QD + seg_[j]*8;
    }
    #pragma unroll
    for (int j=0;j<4;j++){ CPA16(smem_u + stg_[j], Ap[j]); CPA16(smem_u + 32768u + stg_[j], Bp[j]); }
    CPA_COMMIT();
    CPA_WAIT0();
    __syncthreads();

    const int NT = QD/64;  // 16
    for (int kt=0; kt<NT; kt++){
        int slot = kt&1;
        if (kt+1 < NT){
            int kc = (kt+1)*64;
            u32 nb = smem_u + (u32)(slot^1)*16384u;
            #pragma unroll
            for (int j=0;j<4;j++){ CPA16(nb + stg_[j], Ap[j] + kc); CPA16(nb + 32768u + stg_[j], Bp[j] + kc); }
            CPA_COMMIT();
        }
        MMA_COMPUTE(slot);
        if (kt+1 < NT) CPA_WAIT0();
        __syncthreads();
    }

    const float* bp = bias + bn + wn*64 + tig*2;
    #pragma unroll
    for (int mf=0;mf<2;mf++){
        int row = wm*32 + mf*16 + gid;
        __half* c0 = C + (size_t)row*OD + wn*64 + tig*2;
        #pragma unroll
        for (int nf=0;nf<8;nf++){
            float b0 = bp[nf*8], b1 = bp[nf*8+1];
            *(__half2*)(c0 + nf*8)        = __floats2half2_rn(acc[mf][nf][0]+b0, acc[mf][nf][1]+b1);
            *(__half2*)(c0 + nf*8 + 8*OD) = __floats2half2_rn(acc[mf][nf][2]+b0, acc[mf][nf][3]+b1);
        }
    }
}

// -------- prep: cvt inputs to half (4096 blocks) + transpose weights (1152) -
struct PrepArgs {
    const float* q; const float* s; const float* t;
    __half* qh; __half* sh; __half* th;
    const float* wsrc[6]; __half* wdst[6]; int K[6];
};
__global__ void prep_kernel(PrepArgs a){
    __shared__ float tb[64][65];
    int bx = blockIdx.x, tid = threadIdx.x;
    if (bx < 4096){
        int gid = bx*256 + tid;
        const float4* src; uint2* dst; int off;
        if (gid < 524288){ src=(const float4*)a.q; dst=(uint2*)a.qh; off=gid; }
        else if (gid < 786432){ src=(const float4*)a.s; dst=(uint2*)a.sh; off=gid-524288; }
        else { src=(const float4*)a.t; dst=(uint2*)a.th; off=gid-786432; }
        float4 v = src[off];
        uint2 r; __half2* pr=(__half2*)&r;
        pr[0]=__floats2half2_rn(v.x,v.y); pr[1]=__floats2half2_rn(v.z,v.w);
        dst[off]=r;
    } else {
        int local = bx - 4096;
        int mid = local / 192;
        int rem = local % 192;
        int k0 = (rem >> 3) * 64;
        int n0 = (rem & 7) * 64;
        int K = a.K[mid];
        if (k0 >= K) return;
        const float* src = a.wsrc[mid];
        __half* dst = a.wdst[mid];
        #pragma unroll
        for (int j=0;j<16;j++){
            int e = tid + j*256, kk = e>>6, nn = e&63;
            tb[nn][kk] = src[(size_t)(k0+kk)*512 + n0+nn];
        }
        __syncthreads();
        #pragma unroll
        for (int j=0;j<16;j++){
            int e = tid + j*256, nn = e>>6, kk = e&63;
            dst[(size_t)(n0+nn)*K + k0+kk] = __float2half(tb[nn][kk]);
        }
    }
}

// ----------- joint softmax over st=4096 (half in/out) + rowsum --------------
__global__ void softmax_kernel(const __half* __restrict__ wl, __half* __restrict__ wh,
                               float* __restrict__ rowsum) {
    int row = blockIdx.x;
    const uint2* pin = (const uint2*)(wl + (size_t)row * ST_);
    uint2* ph = (uint2*)(wh + (size_t)row * ST_);
    int tid = threadIdx.x;
    float v[4][4];
    float mx = -1e30f;
    #pragma unroll
    for (int i = 0; i < 4; i++) {
        uint2 u = pin[tid + i*256];
        __half2* pu = (__half2*)&u;
        float2 a = __half22float2(pu[0]), b = __half22float2(pu[1]);
        v[i][0]=a.x; v[i][1]=a.y; v[i][2]=b.x; v[i][3]=b.y;
        mx = fmaxf(mx, fmaxf(fmaxf(a.x,a.y), fmaxf(b.x,b.y)));
    }
    __shared__ float red[256];
    red[tid] = mx; __syncthreads();
    #pragma unroll
    for (int s = 128; s > 0; s >>= 1) {
        if (tid < s) red[tid] = fmaxf(red[tid], red[tid+s]);
        __syncthreads();
    }
    mx = red[0];
    __syncthreads();
    float sum = 0.f;
    #pragma unroll
    for (int i = 0; i < 4; i++) {
        float e0 = expf(v[i][0]-mx), e1 = expf(v[i][1]-mx);
        float e2 = expf(v[i][2]-mx), e3 = expf(v[i][3]-mx);
        sum += (e0+e1)+(e2+e3);
        uint2 r; __half2* pr=(__half2*)&r;
        pr[0]=__floats2half2_rn(e0,e1); pr[1]=__floats2half2_rn(e2,e3);
        ph[tid + i*256] = r;
    }
    red[tid] = sum; __syncthreads();
    #pragma unroll
    for (int s = 128; s > 0; s >>= 1) {
        if (tid < s) red[tid] += red[tid+s];
        __syncthreads();
    }
    if (tid == 0) rowsum[row] = red[0];
}

// reduce the 4 half split-K partials, apply 1/rowsum, emit half ctx
__global__ void ctx_reduce(const __half* __restrict__ part, const float* __restrict__ rs,
                           __half* __restrict__ ctx){
    int gid = blockIdx.x*256 + threadIdx.x;       // 4-elem id over 16*128*128
    int n4 = gid & 127; int rest = gid >> 7; int l = rest & 127; int b = rest >> 7;
    const uint2* p = (const uint2*)part;
    float a0=0,a1=0,a2=0,a3=0;
    #pragma unroll
    for (int sp=0; sp<4; sp++){
        uint2 u = p[ ((size_t)(b*4+sp)*128 + l)*128 + n4 ];
        __half2* pu = (__half2*)&u;
        float2 x = __half22float2(pu[0]), y = __half22float2(pu[1]);
        a0+=x.x; a1+=x.y; a2+=y.x; a3+=y.y;
    }
    float inv = 1.f / rs[b*128 + l];
    uint2 r; __half2* pr=(__half2*)&r;
    pr[0]=__floats2half2_rn(a0*inv, a1*inv); pr[1]=__floats2half2_rn(a2*inv, a3*inv);
    ((uint2*)ctx)[gid] = r;
}

// reduce 3 split-K fp32 partials + bias + relu
__global__ void out_reduce(const float* __restrict__ part, const float* __restrict__ bo,
                           float* __restrict__ out){
    int gid = blockIdx.x*256 + threadIdx.x;
    int n4 = gid & 127; int m = gid >> 7;
    float4 p0 = ((const float4*)part)[(size_t)m*128 + n4];
    float4 p1 = ((const float4*)part)[(size_t)(2048+m)*128 + n4];
    float4 p2 = ((const float4*)part)[(size_t)(4096+m)*128 + n4];
    float4 bb = ((const float4*)bo)[n4];
    float4 o = make_float4(fmaxf(p0.x+p1.x+p2.x+bb.x, 0.f), fmaxf(p0.y+p1.y+p2.y+bb.y, 0.f),
                           fmaxf(p0.z+p1.z+p2.z+bb.z, 0.f), fmaxf(p0.w+p1.w+p2.w+bb.w, 0.f));
    ((float4*)out)[gid] = o;
}

// ----------------------------------------------------------------------------
extern "C" void kernel_launch(void* const* d_in, const int* in_sizes, int n_in,
                              void* d_out, int out_size) {
    const float* query = (const float*)d_in[0];
    const float* src   = (const float*)d_in[1];
    const float* trg   = (const float*)d_in[2];
    const float* Wq    = (const float*)d_in[3];
    const float* bq    = (const float*)d_in[4];
    const float* Ws    = (const float*)d_in[5];
    const float* bs    = (const float*)d_in[6];
    const float* Wt    = (const float*)d_in[7];
    const float* bt    = (const float*)d_in[8];
    const float* Wsv   = (const float*)d_in[9];
    const float* bsv   = (const float*)d_in[10];
    const float* Wtv   = (const float*)d_in[11];
    const float* btv   = (const float*)d_in[12];
    const float* Wo    = (const float*)d_in[13];
    const float* bo    = (const float*)d_in[14];
    float* out = (float*)d_out;

    __half *qryh,*srch,*trgh,*qh,*skh,*tkh,*svh,*tvh,*svTh,*tvTh,*wl,*wh,*ctxh,*wTh,*cparth;
    float *grs,*gpart;
    cudaGetSymbolAddress((void**)&qryh, g_qryh);
    cudaGetSymbolAddress((void**)&srch, g_srch);
    cudaGetSymbolAddress((void**)&trgh, g_trgh);
    cudaGetSymbolAddress((void**)&qh,   g_qh);
    cudaGetSymbolAddress((void**)&skh,  g_skh);
    cudaGetSymbolAddress((void**)&tkh,  g_tkh);
    cudaGetSymbolAddress((void**)&svh,  g_svh);
    cudaGetSymbolAddress((void**)&tvh,  g_tvh);
    cudaGetSymbolAddress((void**)&svTh, g_svTh);
    cudaGetSymbolAddress((void**)&tvTh, g_tvTh);
    cudaGetSymbolAddress((void**)&wl,   g_wl);
    cudaGetSymbolAddress((void**)&wh,   g_wh);
    cudaGetSymbolAddress((void**)&ctxh, g_ctxh);
    cudaGetSymbolAddress((void**)&wTh,  g_wTh);
    cudaGetSymbolAddress((void**)&cparth, g_parth);
    cudaGetSymbolAddress((void**)&grs,  g_rs);
    cudaGetSymbolAddress((void**)&gpart,g_part);

    static int smem_set = 0;
    if (!smem_set){
        cudaFuncSetAttribute(l3_kernel,     cudaFuncAttributeMaxDynamicSharedMemorySize, SMEM_MMA);
        cudaFuncSetAttribute(l5_kernel,     cudaFuncAttributeMaxDynamicSharedMemorySize, SMEM_MMA);
        cudaFuncSetAttribute(out_sp2_kernel,cudaFuncAttributeMaxDynamicSharedMemorySize, SMEM_MMA);
        cudaFuncSetAttribute(proj_mma,      cudaFuncAttributeMaxDynamicSharedMemorySize, SMEM_MMA);
        smem_set = 1;
    }

    __half* WqT  = wTh;
    __half* WsT  = wTh + 1*512*1024;
    __half* WtT  = wTh + 2*512*1024;
    __half* WsvT = wTh + 3*512*1024;
    __half* WtvT = wTh + 4*512*1024;
    __half* WoT  = wTh + 5*512*1024;

    PrepArgs pr;
    pr.q=query; pr.s=src; pr.t=trg; pr.qh=qryh; pr.sh=srch; pr.th=trgh;
    pr.wsrc[0]=Wq;  pr.wdst[0]=WqT;  pr.K[0]=1024;
    pr.wsrc[1]=Ws;  pr.wdst[1]=WsT;  pr.K[1]=1024;
    pr.wsrc[2]=Wt;  pr.wdst[2]=WtT;  pr.K[2]=1024;
    pr.wsrc[3]=Wsv; pr.wdst[3]=WsvT; pr.K[3]=1024;
    pr.wsrc[4]=Wtv; pr.wdst[4]=WtvT; pr.K[4]=1024;
    pr.wsrc[5]=Wo;  pr.wdst[5]=WoT;  pr.K[5]=1536;

    ProjArgs pa;
    pa.A[0]=qryh;  pa.A[1]=srch; pa.A[2]=trgh; pa.A[3]=srch;  pa.A[4]=trgh;
    pa.WT[0]=WqT;  pa.WT[1]=WsT; pa.WT[2]=WtT; pa.WT[3]=WsvT; pa.WT[4]=WtvT;
    pa.bias[0]=bq; pa.bias[1]=bs; pa.bias[2]=bt; pa.bias[3]=bsv; pa.bias[4]=btv;
    pa.C[0]=qh;    pa.C[1]=skh;  pa.C[2]=tkh;  pa.C[3]=svh;   pa.C[4]=tvh;

    prep_kernel   <<<4096+1152,    256>>>(pr);
    proj_mma      <<<dim3(4,48),   256, SMEM_MMA>>>(pa);
    l3_kernel     <<<768,          256, SMEM_MMA>>>(qh, skh, tkh, wl, svh, tvh, svTh, tvTh);
    softmax_kernel<<<B_*L_,        256>>>(wl, wh, grs);
    l5_kernel     <<<384,          256, SMEM_MMA>>>(wh, svTh, tvTh, cparth, qryh, WoT, gpart);
    ctx_reduce    <<<1024,         256>>>(cparth, grs, ctxh);
    out_sp2_kernel<<<dim3(4,16),   256, SMEM_MMA>>>(qryh, ctxh, WoT, gpart);
    out_reduce    <<<1024,         256>>>(gpart, bo, out);
}

// round 12
// speedup vs baseline: 2.6698x; 1.0414x over previous
#include <cuda_runtime.h>
#include <cuda_fp16.h>
#include <math.h>

#define B_  16
#define L_  128
#define S_  64
#define T_  64
#define QD  1024
#define HD  512
#define OD  512
#define ST_ 4096

typedef unsigned long long u64;
typedef unsigned int u32;

// ---------------- scratch (static device globals) ---------------------------
__device__ __half g_qryh[B_*L_*QD];
__device__ __half g_srch[B_*S_*QD];
__device__ __half g_trgh[B_*T_*QD];
__device__ __half g_qh  [B_*L_*HD];
__device__ __half g_skh [B_*S_*HD];
__device__ __half g_tkh [B_*T_*HD];
__device__ __half g_svh [B_*S_*HD];
__device__ __half g_tvh [B_*T_*HD];
__device__ __half g_svTh[B_*HD*S_];
__device__ __half g_tvTh[B_*HD*T_];
__device__ __half g_wh  [(size_t)B_*L_*ST_];     // half exp(logit) (16.8 MB)
__device__ float  g_rs  [B_*L_];
__device__ __half g_ctxh[B_*L_*HD];
__device__ __half g_parth[64*128*512];           // ctx split-K partials (half)
__device__ float  g_part[2*2048*512];            // out sp0/sp1 partials (fp32)
__device__ __half g_wTh [5*512*1024 + 512*1536]; // half transposed weights

// ---------------- small helpers ---------------------------------------------
__device__ __forceinline__ u32 smem_u32(const void* p){
    u32 a; asm("{ .reg .u64 t; cvta.to.shared.u64 t, %1; cvt.u32.u64 %0, t; }":"=r"(a):"l"(p));
    return a;
}
__device__ __forceinline__ void mma16(float d[4], const u32 a[4], const u32 b[2]){
    asm volatile("mma.sync.aligned.m16n8k16.row.col.f32.f16.f16.f32 "
        "{%0,%1,%2,%3}, {%4,%5,%6,%7}, {%8,%9}, {%0,%1,%2,%3};"
        : "+f"(d[0]),"+f"(d[1]),"+f"(d[2]),"+f"(d[3])
        : "r"(a[0]),"r"(a[1]),"r"(a[2]),"r"(a[3]),"r"(b[0]),"r"(b[1]));
}
#define LDSM4(r0,r1,r2,r3,addr) \
    asm volatile("ldmatrix.sync.aligned.m8n8.x4.shared.b16 {%0,%1,%2,%3}, [%4];" \
        : "=r"(r0),"=r"(r1),"=r"(r2),"=r"(r3) : "r"(addr))
#define CPA16(dst,src) \
    asm volatile("cp.async.cg.shared.global [%0], [%1], 16;"::"r"(dst),"l"(src):"memory")
#define CPA_COMMIT() asm volatile("cp.async.commit_group;":::"memory")
#define CPA_WAIT0()  asm volatile("cp.async.wait_group 0;":::"memory")

__device__ __forceinline__ uint4 hmul16(uint4 a, uint4 b){
    __half2* pa=(__half2*)&a; __half2* pb=(__half2*)&b;
    uint4 r; __half2* pr=(__half2*)&r;
    pr[0]=__hmul2(pa[0],pb[0]); pr[1]=__hmul2(pa[1],pb[1]);
    pr[2]=__hmul2(pa[2],pb[2]); pr[3]=__hmul2(pa[3],pb[3]);
    return r;
}
__device__ __forceinline__ uint4 hscale16(uint4 a, __half sc){
    __half2 s2 = __half2half2(sc);
    __half2* pa=(__half2*)&a;
    uint4 r; __half2* pr=(__half2*)&r;
    pr[0]=__hmul2(pa[0],s2); pr[1]=__hmul2(pa[1],s2);
    pr[2]=__hmul2(pa[2],s2); pr[3]=__hmul2(pa[3],s2);
    return r;
}

#define SMEM_MMA 65536

#define MMA_PROLOG() \
    int tid=threadIdx.x, lane=tid&31, wid=tid>>5; \
    int wm = wid&3, wn = wid>>2; \
    int gid = lane>>2, tig = lane&3; \
    int l7 = lane&7, lq = lane>>3; \
    u32 smem_u = smem_u32(dsm); \
    int a_sh = lq>>1, b_sh = lq&1; \
    u32 a_row[2], b_row[4]; \
    _Pragma("unroll") \
    for (int mf=0;mf<2;mf++) a_row[mf] = (u32)(wm*32 + mf*16 + (lq&1)*8 + l7)*128u; \
    _Pragma("unroll") \
    for (int p=0;p<4;p++)    b_row[p]  = (u32)(wn*64 + (2*p + (lq>>1))*8 + l7)*128u; \
    int row_[4], seg_[4]; u32 stg_[4]; \
    _Pragma("unroll") \
    for (int j=0;j<4;j++){ int f4 = tid + j*256; row_[j]=f4>>3; seg_[j]=f4&7; \
        stg_[j] = (u32)(row_[j]*128 + ((seg_[j]^(row_[j]&7))<<4)); } \
    float acc[2][8][4]; \
    _Pragma("unroll") \
    for(int mf=0;mf<2;mf++) \
        _Pragma("unroll") \
        for(int nf=0;nf<8;nf++) \
            _Pragma("unroll") \
            for(int r=0;r<4;r++) acc[mf][nf][r]=0.f;

#define MMA_COMPUTE(slot) do { \
    u32 Ab_ = smem_u + (u32)(slot)*16384u; \
    u32 Bb_ = smem_u + 32768u + (u32)(slot)*16384u; \
    _Pragma("unroll") \
    for (int ks=0; ks<4; ks++){ \
        u32 asg = (u32)(((ks*2 + a_sh) ^ l7) << 4); \
        u32 bsg = (u32)(((ks*2 + b_sh) ^ l7) << 4); \
        u32 afr[2][4]; u32 bfr[8][2]; \
        _Pragma("unroll") \
        for (int mf=0;mf<2;mf++) \
            LDSM4(afr[mf][0],afr[mf][1],afr[mf][2],afr[mf][3], Ab_ + a_row[mf] + asg); \
        _Pragma("unroll") \
        for (int p=0;p<4;p++) \
            LDSM4(bfr[2*p][0],bfr[2*p][1],bfr[2*p+1][0],bfr[2*p+1][1], Bb_ + b_row[p] + bsg); \
        _Pragma("unroll") \
        for (int mf=0;mf<2;mf++) \
            _Pragma("unroll") \
            for (int nf=0;nf<8;nf++) mma16(acc[mf][nf], afr[mf], bfr[nf]); \
    } \
} while(0)

#define STS_B(slot, j, v4) \
    *(uint4*)((char*)dsm + 32768 + (u32)(slot)*16384u + stg_[j]) = (v4)

// ===== tri body: wh = exp(Q @ (sk.*tk)^T / sqrt(HD)), rowsum atomics ========
__device__ __forceinline__ void tri_body(const __half* __restrict__ q,
        const __half* __restrict__ sk, const __half* __restrict__ tk,
        __half* __restrict__ w, float* __restrict__ rs, int tile, int b, float* dsm){
    const __half* qb = q + (size_t)b*L_*HD;
    MMA_PROLOG();
    const __half* skp[4]; const __half* tkp[4]; const __half* qp[4];
    #pragma unroll
    for (int j=0;j<4;j++){
        int st = tile*128 + row_[j];
        skp[j] = sk + (size_t)(b*S_ + (st>>6))*HD + seg_[j]*8;
        tkp[j] = tk + (size_t)(b*T_ + (st&63))*HD + seg_[j]*8;
        qp[j]  = qb + (size_t)row_[j]*HD + seg_[j]*8;
    }
    #pragma unroll
    for (int j=0;j<4;j++) CPA16(smem_u + stg_[j], qp[j]);
    CPA_COMMIT();
    uint4 pb[4];
    #pragma unroll
    for (int j=0;j<4;j++)
        pb[j] = hmul16(*(const uint4*)tkp[j], *(const uint4*)skp[j]);
    #pragma unroll
    for (int j=0;j<4;j++) STS_B(0, j, pb[j]);
    CPA_WAIT0();
    __syncthreads();

    const int NT = HD/64;   // 8
    for (int kt=0; kt<NT; kt++){
        int slot = kt&1;
        if (kt+1 < NT){
            int kc = (kt+1)*64;
            u32 nb = smem_u + (u32)(slot^1)*16384u;
            #pragma unroll
            for (int j=0;j<4;j++) CPA16(nb + stg_[j], qp[j] + kc);
            CPA_COMMIT();
            #pragma unroll
            for (int j=0;j<4;j++)
                pb[j] = hmul16(*(const uint4*)(tkp[j]+kc), *(const uint4*)(skp[j]+kc));
        }
        MMA_COMPUTE(slot);
        if (kt+1 < NT){
            #pragma unroll
            for (int j=0;j<4;j++) STS_B(slot^1, j, pb[j]);
            CPA_WAIT0();
        }
        __syncthreads();
    }

    // epilogue: exp + half store + per-row partial sums (atomicAdd)
    const float scale = 0.044194173824159216f;  // 1/sqrt(512)
    #pragma unroll
    for (int mf=0;mf<2;mf++){
        int row = wm*32 + mf*16 + gid;
        __half* w0 = w + ((size_t)(b*L_+row))*ST_ + tile*128 + wn*64 + tig*2;
        float s0 = 0.f, s1 = 0.f;
        #pragma unroll
        for (int nf=0;nf<8;nf++){
            float e0 = __expf(acc[mf][nf][0]*scale);
            float e1 = __expf(acc[mf][nf][1]*scale);
            float e2 = __expf(acc[mf][nf][2]*scale);
            float e3 = __expf(acc[mf][nf][3]*scale);
            s0 += e0 + e1; s1 += e2 + e3;
            *(__half2*)(w0 + nf*8)          = __floats2half2_rn(e0, e1);
            *(__half2*)(w0 + nf*8 + 8*ST_)  = __floats2half2_rn(e2, e3);
        }
        // reduce across tig lanes (bits 0,1 of lane)
        s0 += __shfl_xor_sync(0xffffffffu, s0, 1);
        s0 += __shfl_xor_sync(0xffffffffu, s0, 2);
        s1 += __shfl_xor_sync(0xffffffffu, s1, 1);
        s1 += __shfl_xor_sync(0xffffffffu, s1, 2);
        if (tig == 0){
            atomicAdd(&rs[b*L_ + row],     s0);
            atomicAdd(&rs[b*L_ + row + 8], s1);
        }
    }
}

// ====== ctx body: parth[b,sp][128l x 128k] = E_chunk @ (svT.*tvT)^T =========
__device__ __forceinline__ void ctx_body(const __half* __restrict__ E,
        const __half* __restrict__ svT, const __half* __restrict__ tvT,
        __half* __restrict__ part, int nt, int sp, int b, float* dsm){
    int n0 = nt*128;
    const __half* Eb  = E   + (size_t)b*L_*ST_ + sp*1024;
    const __half* svb = svT + ((size_t)b*HD + n0)*S_;
    const __half* tvb = tvT + ((size_t)b*HD + n0)*T_;
    MMA_PROLOG();
    const __half* Ep[4];
    #pragma unroll
    for (int j=0;j<4;j++) Ep[j] = Eb + (size_t)row_[j]*ST_ + seg_[j]*8;

    #pragma unroll
    for (int j=0;j<4;j++) CPA16(smem_u + stg_[j], Ep[j]);
    CPA_COMMIT();
    uint4 pb[4];
    {   int s = sp*16;
        #pragma unroll
        for (int j=0;j<4;j++){
            uint4 t4 = *(const uint4*)(tvb + (size_t)row_[j]*T_ + seg_[j]*8);
            pb[j] = hscale16(t4, svb[(size_t)row_[j]*S_ + s]);
        }
    }
    #pragma unroll
    for (int j=0;j<4;j++) STS_B(0, j, pb[j]);
    CPA_WAIT0();
    __syncthreads();

    const int NT = 1024/64;  // 16
    for (int kt=0; kt<NT; kt++){
        int slot = kt&1;
        if (kt+1 < NT){
            int kc = (kt+1)*64;
            u32 nb = smem_u + (u32)(slot^1)*16384u;
            #pragma unroll
            for (int j=0;j<4;j++) CPA16(nb + stg_[j], Ep[j] + kc);
            CPA_COMMIT();
            int s = sp*16 + kt + 1;
            #pragma unroll
            for (int j=0;j<4;j++){
                uint4 t4 = *(const uint4*)(tvb + (size_t)row_[j]*T_ + seg_[j]*8);
                pb[j] = hscale16(t4, svb[(size_t)row_[j]*S_ + s]);
            }
        }
        MMA_COMPUTE(slot);
        if (kt+1 < NT){
            #pragma unroll
            for (int j=0;j<4;j++) STS_B(slot^1, j, pb[j]);
            CPA_WAIT0();
        }
        __syncthreads();
    }

    #pragma unroll
    for (int mf=0;mf<2;mf++){
        int row = wm*32 + mf*16 + gid;
        __half* p0 = part + ((size_t)(b*4+sp)*128 + row)*512 + n0 + wn*64 + tig*2;
        #pragma unroll
        for (int nf=0;nf<8;nf++){
            *(__half2*)(p0 + nf*8)         = __floats2half2_rn(acc[mf][nf][0], acc[mf][nf][1]);
            *(__half2*)(p0 + nf*8 + 8*512) = __floats2half2_rn(acc[mf][nf][2], acc[mf][nf][3]);
        }
    }
}

// ===== out partial body (sp 0/1): fp32 partials of query-half GEMM ==========
__device__ __forceinline__ void out_part_body(const __half* __restrict__ query,
        const __half* __restrict__ WoT, float* __restrict__ part,
        int bnI, int bmI, int sp, float* dsm){
    int bn = bnI*128, bm = bmI*128;
    const __half* Ab = query + (size_t)bm*QD + sp*512;
    const __half* Bw = WoT + (size_t)bn*1536 + sp*512;
    MMA_PROLOG();
    const __half* Ap[4]; const __half* Bp[4];
    #pragma unroll
    for (int j=0;j<4;j++){
        Ap[j] = Ab + (size_t)row_[j]*QD + seg_[j]*8;
        Bp[j] = Bw + (size_t)row_[j]*1536 + seg_[j]*8;
    }
    #pragma unroll
    for (int j=0;j<4;j++){ CPA16(smem_u + stg_[j], Ap[j]); CPA16(smem_u + 32768u + stg_[j], Bp[j]); }
    CPA_COMMIT();
    CPA_WAIT0();
    __syncthreads();

    const int NT = 512/64;  // 8
    for (int kt=0; kt<NT; kt++){
        int slot = kt&1;
        if (kt+1 < NT){
            int kc = (kt+1)*64;
            u32 nb = smem_u + (u32)(slot^1)*16384u;
            #pragma unroll
            for (int j=0;j<4;j++){ CPA16(nb + stg_[j], Ap[j] + kc); CPA16(nb + 32768u + stg_[j], Bp[j] + kc); }
            CPA_COMMIT();
        }
        MMA_COMPUTE(slot);
        if (kt+1 < NT) CPA_WAIT0();
        __syncthreads();
    }

    #pragma unroll
    for (int mf=0;mf<2;mf++){
        int row = wm*32 + mf*16 + gid;
        float* p0 = part + ((size_t)sp*2048 + bm + row)*512 + bn + wn*64 + tig*2;
        #pragma unroll
        for (int nf=0;nf<8;nf++){
            *(float2*)(p0 + nf*8)         = make_float2(acc[mf][nf][0], acc[mf][nf][1]);
            *(float2*)(p0 + nf*8 + 8*512) = make_float2(acc[mf][nf][2], acc[mf][nf][3]);
        }
    }
}

// ===== out final (sp=2, ctx-half) + fused reduce of sp0/sp1 + bias + relu ===
__global__ __launch_bounds__(256,2) void out_final_kernel(const __half* __restrict__ ctx,
        const __half* __restrict__ WoT, const float* __restrict__ part,
        const float* __restrict__ bo, float* __restrict__ out){
    extern __shared__ __align__(16) float dsm[];
    int bn = blockIdx.x*128, bm = blockIdx.y*128;
    const __half* Ab = ctx + (size_t)bm*HD;
    const __half* Bw = WoT + (size_t)bn*1536 + 2*512;
    MMA_PROLOG();
    const __half* Ap[4]; const __half* Bp[4];
    #pragma unroll
    for (int j=0;j<4;j++){
        Ap[j] = Ab + (size_t)row_[j]*HD + seg_[j]*8;
        Bp[j] = Bw + (size_t)row_[j]*1536 + seg_[j]*8;
    }
    #pragma unroll
    for (int j=0;j<4;j++){ CPA16(smem_u + stg_[j], Ap[j]); CPA16(smem_u + 32768u + stg_[j], Bp[j]); }
    CPA_COMMIT();
    CPA_WAIT0();
    __syncthreads();

    const int NT = 512/64;  // 8
    for (int kt=0; kt<NT; kt++){
        int slot = kt&1;
        if (kt+1 < NT){
            int kc = (kt+1)*64;
            u32 nb = smem_u + (u32)(slot^1)*16384u;
            #pragma unroll
            for (int j=0;j<4;j++){ CPA16(nb + stg_[j], Ap[j] + kc); CPA16(nb + 32768u + stg_[j], Bp[j] + kc); }
            CPA_COMMIT();
        }
        MMA_COMPUTE(slot);
        if (kt+1 < NT) CPA_WAIT0();
        __syncthreads();
    }

    const float* bp = bo + bn + wn*64 + tig*2;
    #pragma unroll
    for (int mf=0;mf<2;mf++){
        int row = wm*32 + mf*16 + gid;
        int m0 = bm + row;
        const float* q0 = part + (size_t)m0*512 + bn + wn*64 + tig*2;
        const float* q1 = part + (size_t)(2048 + m0)*512 + bn + wn*64 + tig*2;
        float* o0 = out + (size_t)m0*OD + bn + wn*64 + tig*2;
        #pragma unroll
        for (int nf=0;nf<8;nf++){
            float b0 = bp[nf*8], b1 = bp[nf*8+1];
            {   float2 pA = *(const float2*)(q0 + nf*8);
                float2 pB = *(const float2*)(q1 + nf*8);
                *(float2*)(o0 + nf*8) = make_float2(
                    fmaxf(acc[mf][nf][0] + pA.x + pB.x + b0, 0.f),
                    fmaxf(acc[mf][nf][1] + pA.y + pB.y + b1, 0.f));
            }
            {   float2 pA = *(const float2*)(q0 + nf*8 + 8*512);
                float2 pB = *(const float2*)(q1 + nf*8 + 8*512);
                *(float2*)(o0 + nf*8 + 8*OD) = make_float2(
                    fmaxf(acc[mf][nf][2] + pA.x + pB.x + b0, 0.f),
                    fmaxf(acc[mf][nf][3] + pA.y + pB.y + b1, 0.f));
            }
        }
    }
}

// -------- transpose_vals body (uses dynamic smem) ---------------------------
__device__ __forceinline__ void tvals_body(const __half* __restrict__ sv,
        const __half* __restrict__ tv, __half* __restrict__ svT, __half* __restrict__ tvT,
        int k0t, int b, int z, float* dsm){
    __half (*tilebuf)[65] = ( __half(*)[65] )dsm;
    int k0 = k0t*64;
    const __half* src = z ? tv : sv;
    __half* dst = z ? tvT : svT;
    int tid = threadIdx.x;
    #pragma unroll
    for (int j = 0; j < 16; j++){
        int e = tid + j*256, s = e>>6, k = e&63;
        tilebuf[k][s] = src[(size_t)(b*64 + s)*HD + k0 + k];
    }
    __syncthreads();
    #pragma unroll
    for (int j = 0; j < 16; j++){
        int e = tid + j*256, k = e>>6, s = e&63;
        dst[(size_t)(b*HD + k0 + k)*64 + s] = tilebuf[k][s];
    }
}

// ============ merged launch 3: tri (512 blocks) + transpose_vals (256) ======
__global__ __launch_bounds__(256,2) void l3_kernel(const __half* __restrict__ q,
        const __half* __restrict__ sk, const __half* __restrict__ tk,
        __half* __restrict__ w, float* __restrict__ rs, const __half* __restrict__ sv,
        const __half* __restrict__ tv, __half* __restrict__ svT, __half* __restrict__ tvT){
    extern __shared__ __align__(16) float dsm[];
    int bx = blockIdx.x;
    if (bx < 512){
        tri_body(q, sk, tk, w, rs, bx & 31, bx >> 5, dsm);
    } else {
        int local = bx - 512;
        tvals_body(sv, tv, svT, tvT, local & 7, (local >> 3) & 15, local >> 7, dsm);
    }
}

// ============ merged launch 4: ctx (256 blocks) + out sp0,1 (128) ===========
__global__ __launch_bounds__(256,2) void l5_kernel(const __half* __restrict__ E,
        const __half* __restrict__ svT, const __half* __restrict__ tvT,
        __half* __restrict__ cpart, const __half* __restrict__ query,
        const __half* __restrict__ WoT, float* __restrict__ opart){
    extern __shared__ __align__(16) float dsm[];
    int bx = blockIdx.x;
    if (bx < 256){
        int nt = bx & 3, sp = (bx >> 2) & 3, b = bx >> 4;
        ctx_body(E, svT, tvT, cpart, nt, sp, b, dsm);
    } else {
        int local = bx - 256;
        out_part_body(query, WoT, opart, local & 3, (local >> 2) & 15, local >> 6, dsm);
    }
}

// ============ projections: C = A[Mx1024] @ W + bias (half out) ==============
struct ProjArgs {
    const __half* A[5];
    const __half* WT[5];
    const float*  bias[5];
    __half*       C[5];
};

__global__ __launch_bounds__(256,2) void proj_mma(ProjArgs args){
    extern __shared__ __align__(16) float dsm[];
    int y = blockIdx.y;
    int task, mt;
    if (y < 16){ task=0; mt=y; } else { task = 1 + ((y-16)>>3); mt = (y-16)&7; }
    int bm = mt*128, bn = blockIdx.x*128;
    const __half* Ab   = args.A[task]  + (size_t)bm*QD;
    const __half* Bw   = args.WT[task] + (size_t)bn*QD;
    const float*  bias = args.bias[task];
    __half*       C    = args.C[task]  + (size_t)bm*OD + bn;
    MMA_PROLOG();
    const __half* Ap[4]; const __half* Bp[4];
    #pragma unroll
    for (int j=0;j<4;j++){
        Ap[j] = Ab + (size_t)row_[j]*QD + seg_[j]*8;
        Bp[j] = Bw + (size_t)row_[j]*QD + seg_[j]*8;
    }
    #pragma unroll
    for (int j=0;j<4;j++){ CPA16(smem_u + stg_[j], Ap[j]); CPA16(smem_u + 32768u + stg_[j], Bp[j]); }
    CPA_COMMIT();
    CPA_WAIT0();
    __syncthreads();

    const int NT = QD/64;  // 16
    for (int kt=0; kt<NT; kt++){
        int slot = kt&1;
        if (kt+1 < NT){
            int kc = (kt+1)*64;
            u32 nb = smem_u + (u32)(slot^1)*16384u;
            #pragma unroll
            for (int j=0;j<4;j++){ CPA16(nb + stg_[j], Ap[j] + kc); CPA16(nb + 32768u + stg_[j], Bp[j] + kc); }
            CPA_COMMIT();
        }
        MMA_COMPUTE(slot);
        if (kt+1 < NT) CPA_WAIT0();
        __syncthreads();
    }

    const float* bp = bias + bn + wn*64 + tig*2;
    #pragma unroll
    for (int mf=0;mf<2;mf++){
        int row = wm*32 + mf*16 + gid;
        __half* c0 = C + (size_t)row*OD + wn*64 + tig*2;
        #pragma unroll
        for (int nf=0;nf<8;nf++){
            float b0 = bp[nf*8], b1 = bp[nf*8+1];
            *(__half2*)(c0 + nf*8)        = __floats2half2_rn(acc[mf][nf][0]+b0, acc[mf][nf][1]+b1);
            *(__half2*)(c0 + nf*8 + 8*OD) = __floats2half2_rn(acc[mf][nf][2]+b0, acc[mf][nf][3]+b1);
        }
    }
}

// -------- prep: cvt inputs (4096) + transpose weights (1152) + zero rs ------
struct PrepArgs {
    const float* q; const float* s; const float* t;
    __half* qh; __half* sh; __half* th;
    const float* wsrc[6]; __half* wdst[6]; int K[6];
    float* rs;
};
__global__ void prep_kernel(PrepArgs a){
    __shared__ float tb[64][65];
    int bx = blockIdx.x, tid = threadIdx.x;
    if (bx < 4096){
        if (bx == 0){
            #pragma unroll
            for (int i=0;i<8;i++) a.rs[tid + i*256] = 0.f;
        }
        int gid = bx*256 + tid;
        const float4* src; uint2* dst; int off;
        if (gid < 524288){ src=(const float4*)a.q; dst=(uint2*)a.qh; off=gid; }
        else if (gid < 786432){ src=(const float4*)a.s; dst=(uint2*)a.sh; off=gid-524288; }
        else { src=(const float4*)a.t; dst=(uint2*)a.th; off=gid-786432; }
        float4 v = src[off];
        uint2 r; __half2* pr=(__half2*)&r;
        pr[0]=__floats2half2_rn(v.x,v.y); pr[1]=__floats2half2_rn(v.z,v.w);
        dst[off]=r;
    } else {
        int local = bx - 4096;
        int mid = local / 192;
        int rem = local % 192;
        int k0 = (rem >> 3) * 64;
        int n0 = (rem & 7) * 64;
        int K = a.K[mid];
        if (k0 >= K) return;
        const float* src = a.wsrc[mid];
        __half* dst = a.wdst[mid];
        #pragma unroll
        for (int j=0;j<16;j++){
            int e = tid + j*256, kk = e>>6, nn = e&63;
            tb[nn][kk] = src[(size_t)(k0+kk)*512 + n0+nn];
        }
        __syncthreads();
        #pragma unroll
        for (int j=0;j<16;j++){
            int e = tid + j*256, nn = e>>6, kk = e&63;
            dst[(size_t)(n0+nn)*K + k0+kk] = __float2half(tb[nn][kk]);
        }
    }
}

// reduce the 4 half split-K partials, apply 1/rowsum, emit half ctx
__global__ void ctx_reduce(const __half* __restrict__ part, const float* __restrict__ rs,
                           __half* __restrict__ ctx){
    int gid = blockIdx.x*256 + threadIdx.x;       // 4-elem id over 16*128*128
    int n4 = gid & 127; int rest = gid >> 7; int l = rest & 127; int b = rest >> 7;
    const uint2* p = (const uint2*)part;
    float a0=0,a1=0,a2=0,a3=0;
    #pragma unroll
    for (int sp=0; sp<4; sp++){
        uint2 u = p[ ((size_t)(b*4+sp)*128 + l)*128 + n4 ];
        __half2* pu = (__half2*)&u;
        float2 x = __half22float2(pu[0]), y = __half22float2(pu[1]);
        a0+=x.x; a1+=x.y; a2+=y.x; a3+=y.y;
    }
    float inv = 1.f / rs[b*128 + l];
    uint2 r; __half2* pr=(__half2*)&r;
    pr[0]=__floats2half2_rn(a0*inv, a1*inv); pr[1]=__floats2half2_rn(a2*inv, a3*inv);
    ((uint2*)ctx)[gid] = r;
}

// ----------------------------------------------------------------------------
extern "C" void kernel_launch(void* const* d_in, const int* in_sizes, int n_in,
                              void* d_out, int out_size) {
    const float* query = (const float*)d_in[0];
    const float* src   = (const float*)d_in[1];
    const float* trg   = (const float*)d_in[2];
    const float* Wq    = (const float*)d_in[3];
    const float* bq    = (const float*)d_in[4];
    const float* Ws    = (const float*)d_in[5];
    const float* bs    = (const float*)d_in[6];
    const float* Wt    = (const float*)d_in[7];
    const float* bt    = (const float*)d_in[8];
    const float* Wsv   = (const float*)d_in[9];
    const float* bsv   = (const float*)d_in[10];
    const float* Wtv   = (const float*)d_in[11];
    const float* btv   = (const float*)d_in[12];
    const float* Wo    = (const float*)d_in[13];
    const float* bo    = (const float*)d_in[14];
    float* out = (float*)d_out;

    __half *qryh,*srch,*trgh,*qh,*skh,*tkh,*svh,*tvh,*svTh,*tvTh,*wh,*ctxh,*wTh,*cparth;
    float *grs,*gpart;
    cudaGetSymbolAddress((void**)&qryh, g_qryh);
    cudaGetSymbolAddress((void**)&srch, g_srch);
    cudaGetSymbolAddress((void**)&trgh, g_trgh);
    cudaGetSymbolAddress((void**)&qh,   g_qh);
    cudaGetSymbolAddress((void**)&skh,  g_skh);
    cudaGetSymbolAddress((void**)&tkh,  g_tkh);
    cudaGetSymbolAddress((void**)&svh,  g_svh);
    cudaGetSymbolAddress((void**)&tvh,  g_tvh);
    cudaGetSymbolAddress((void**)&svTh, g_svTh);
    cudaGetSymbolAddress((void**)&tvTh, g_tvTh);
    cudaGetSymbolAddress((void**)&wh,   g_wh);
    cudaGetSymbolAddress((void**)&ctxh, g_ctxh);
    cudaGetSymbolAddress((void**)&wTh,  g_wTh);
    cudaGetSymbolAddress((void**)&cparth, g_parth);
    cudaGetSymbolAddress((void**)&grs,  g_rs);
    cudaGetSymbolAddress((void**)&gpart,g_part);

    static int smem_set = 0;
    if (!smem_set){
        cudaFuncSetAttribute(l3_kernel,       cudaFuncAttributeMaxDynamicSharedMemorySize, SMEM_MMA);
        cudaFuncSetAttribute(l5_kernel,       cudaFuncAttributeMaxDynamicSharedMemorySize, SMEM_MMA);
        cudaFuncSetAttribute(out_final_kernel,cudaFuncAttributeMaxDynamicSharedMemorySize, SMEM_MMA);
        cudaFuncSetAttribute(proj_mma,        cudaFuncAttributeMaxDynamicSharedMemorySize, SMEM_MMA);
        smem_set = 1;
    }

    __half* WqT  = wTh;
    __half* WsT  = wTh + 1*512*1024;
    __half* WtT  = wTh + 2*512*1024;
    __half* WsvT = wTh + 3*512*1024;
    __half* WtvT = wTh + 4*512*1024;
    __half* WoT  = wTh + 5*512*1024;

    PrepArgs pr;
    pr.q=query; pr.s=src; pr.t=trg; pr.qh=qryh; pr.sh=srch; pr.th=trgh;
    pr.wsrc[0]=Wq;  pr.wdst[0]=WqT;  pr.K[0]=1024;
    pr.wsrc[1]=Ws;  pr.wdst[1]=WsT;  pr.K[1]=1024;
    pr.wsrc[2]=Wt;  pr.wdst[2]=WtT;  pr.K[2]=1024;
    pr.wsrc[3]=Wsv; pr.wdst[3]=WsvT; pr.K[3]=1024;
    pr.wsrc[4]=Wtv; pr.wdst[4]=WtvT; pr.K[4]=1024;
    pr.wsrc[5]=Wo;  pr.wdst[5]=WoT;  pr.K[5]=1536;
    pr.rs = grs;

    ProjArgs pa;
    pa.A[0]=qryh;  pa.A[1]=srch; pa.A[2]=trgh; pa.A[3]=srch;  pa.A[4]=trgh;
    pa.WT[0]=WqT;  pa.WT[1]=WsT; pa.WT[2]=WtT; pa.WT[3]=WsvT; pa.WT[4]=WtvT;
    pa.bias[0]=bq; pa.bias[1]=bs; pa.bias[2]=bt; pa.bias[3]=bsv; pa.bias[4]=btv;
    pa.C[0]=qh;    pa.C[1]=skh;  pa.C[2]=tkh;  pa.C[3]=svh;   pa.C[4]=tvh;

    prep_kernel     <<<4096+1152,  256>>>(pr);
    proj_mma        <<<dim3(4,48), 256, SMEM_MMA>>>(pa);
    l3_kernel       <<<768,        256, SMEM_MMA>>>(qh, skh, tkh, wh, grs, svh, tvh, svTh, tvTh);
    l5_kernel       <<<384,        256, SMEM_MMA>>>(wh, svTh, tvTh, cparth, qryh, WoT, gpart);
    ctx_reduce      <<<1024,       256>>>(cparth, grs, ctxh);
    out_final_kernel<<<dim3(4,16), 256, SMEM_MMA>>>(ctxh, WoT, gpart, bo, out);
}